// round 2
// baseline (speedup 1.0000x reference)
#include <cuda_runtime.h>

#define NN 50000
#define NE 800000
#define D  128

// ---------------- scratch (static device globals; no allocation) -------------
__device__ float g_h  [NN * D];   // GEMM output (pre-aggregation)
__device__ float g_out[NN * D];   // aggregated output / next-layer input
__device__ float g_norm[NE];
__device__ int   g_src [NE];
__device__ int   g_dst [NE];
__device__ float g_deg [NN];
__device__ float g_dinv[NN];
__device__ int   g_is64;          // 1 if edge_index is int64, 0 if int32

// ---------------- packed f32x2 helpers (Blackwell) ---------------------------
__device__ __forceinline__ unsigned long long pk2(float lo, float hi) {
    unsigned long long r;
    asm("mov.b64 %0, {%1, %2};" : "=l"(r) : "f"(lo), "f"(hi));
    return r;
}
__device__ __forceinline__ void fma2(unsigned long long& d,
                                     unsigned long long a,
                                     unsigned long long b) {
    asm("fma.rn.f32x2 %0, %1, %2, %0;" : "+l"(d) : "l"(a), "l"(b));
}
__device__ __forceinline__ float2 up2(unsigned long long v) {
    float2 f;
    asm("mov.b64 {%0, %1}, %2;" : "=f"(f.x), "=f"(f.y) : "l"(v));
    return f;
}

// ---------------- edge-index dtype detection ----------------------------------
// int64 values < 2^31 stored little-endian look like (lo, 0) int32 pairs.
// Random int32 indices in [0, 50000) cannot have 64 consecutive zero odd-words.
__global__ void k_detect(const int* __restrict__ ei32, int E) {
    int sample = 64;
    int odd_zero = 1;
    for (int i = 0; i < sample; i++) {
        if (ei32[2 * i + 1] != 0) { odd_zero = 0; break; }
    }
    g_is64 = odd_zero;
}

// ---------------- degree / norm prep -----------------------------------------
__global__ void k_deg_init(int n) {
    int i = blockIdx.x * blockDim.x + threadIdx.x;
    if (i < n) g_deg[i] = 1.0f;   // self-loop weight
}

// decode src/dst (either dtype), store int32 copies, accumulate weighted degree
__global__ void k_deg_accum(const void* __restrict__ ei_raw,
                            const float* __restrict__ w, int E, int n) {
    int e = blockIdx.x * blockDim.x + threadIdx.x;
    if (e >= E) return;
    int s, d;
    if (g_is64) {
        const long long* ei = (const long long*)ei_raw;
        s = (int)ei[e];
        d = (int)ei[E + e];
    } else {
        const int* ei = (const int*)ei_raw;
        s = ei[e];
        d = ei[E + e];
    }
    // defensive clamp: invalid edges become self-edges on node 0 with weight 0 effect
    if ((unsigned)s >= (unsigned)n) s = 0;
    if ((unsigned)d >= (unsigned)n) d = 0;
    g_src[e] = s;
    g_dst[e] = d;
    atomicAdd(&g_deg[d], w[e]);
}

__global__ void k_dinv(int n) {
    int i = blockIdx.x * blockDim.x + threadIdx.x;
    if (i < n) g_dinv[i] = rsqrtf(g_deg[i]);   // deg >= 1 always (self loop)
}

__global__ void k_norm(const float* __restrict__ w, int E) {
    int e = blockIdx.x * blockDim.x + threadIdx.x;
    if (e < E) g_norm[e] = g_dinv[g_src[e]] * w[e] * g_dinv[g_dst[e]];
}

// ---------------- GEMM: out[r][c] = act(in[r]) . W[:,c] (+bias) --------------
// 256 threads: tx=lane (4 cols each), ty=warp (4 rows each) -> 32 rows/block.
template <bool RELU, bool BIAS>
__global__ void __launch_bounds__(256)
k_gemm(const float* __restrict__ in, const float* __restrict__ W,
       const float* __restrict__ bias, float* __restrict__ out, int n) {
    const int tx = threadIdx.x & 31;
    const int ty = threadIdx.x >> 5;
    const int c0 = tx * 4;
    const int r0 = blockIdx.x * 32 + ty * 4;

    unsigned long long acc[4][2];
#pragma unroll
    for (int i = 0; i < 4; i++) { acc[i][0] = 0ull; acc[i][1] = 0ull; }

    for (int k = 0; k < D; k += 4) {
        float4 xv[4];
#pragma unroll
        for (int i = 0; i < 4; i++) {
            int r = r0 + i;
            if (r < n) {
                xv[i] = *reinterpret_cast<const float4*>(in + (size_t)r * D + k);
                if (RELU) {
                    xv[i].x = fmaxf(xv[i].x, 0.0f);
                    xv[i].y = fmaxf(xv[i].y, 0.0f);
                    xv[i].z = fmaxf(xv[i].z, 0.0f);
                    xv[i].w = fmaxf(xv[i].w, 0.0f);
                }
            } else {
                xv[i] = make_float4(0.f, 0.f, 0.f, 0.f);
            }
        }
#pragma unroll
        for (int kk = 0; kk < 4; kk++) {
            float4 wv = *reinterpret_cast<const float4*>(W + (size_t)(k + kk) * D + c0);
            unsigned long long b01 = pk2(wv.x, wv.y);
            unsigned long long b23 = pk2(wv.z, wv.w);
#pragma unroll
            for (int i = 0; i < 4; i++) {
                float a = (kk == 0) ? xv[i].x : (kk == 1) ? xv[i].y
                        : (kk == 2) ? xv[i].z : xv[i].w;
                unsigned long long a2 = pk2(a, a);
                fma2(acc[i][0], a2, b01);
                fma2(acc[i][1], a2, b23);
            }
        }
    }

#pragma unroll
    for (int i = 0; i < 4; i++) {
        int r = r0 + i;
        if (r >= n) continue;
        float2 p0 = up2(acc[i][0]);
        float2 p1 = up2(acc[i][1]);
        float4 o = make_float4(p0.x, p0.y, p1.x, p1.y);
        if (BIAS) {
            o.x += bias[c0 + 0];
            o.y += bias[c0 + 1];
            o.z += bias[c0 + 2];
            o.w += bias[c0 + 3];
        }
        *reinterpret_cast<float4*>(out + (size_t)r * D + c0) = o;
    }
}

// ---------------- self-loop + bias init: out = h * dinv^2 + b ----------------
__global__ void k_self_bias(const float* __restrict__ bias, int n) {
    int idx = blockIdx.x * blockDim.x + threadIdx.x;   // one float4 each
    int total = n * (D / 4);
    if (idx >= total) return;
    int i  = idx >> 5;          // node (D/4 == 32)
    int j4 = (idx & 31) * 4;    // column base
    float di = g_dinv[i];
    float s  = di * di;         // self-loop norm = 1/deg
    float4 h = *reinterpret_cast<const float4*>(g_h + (size_t)i * D + j4);
    float4 b = *reinterpret_cast<const float4*>(bias + j4);
    float4 o = make_float4(fmaf(h.x, s, b.x), fmaf(h.y, s, b.y),
                           fmaf(h.z, s, b.z), fmaf(h.w, s, b.w));
    *reinterpret_cast<float4*>(g_out + (size_t)i * D + j4) = o;
}

// ---------------- edge scatter: out[dst] += h[src] * norm (warp per edge) ----
__global__ void __launch_bounds__(256)
k_scatter(int E) {
    int e    = (blockIdx.x * blockDim.x + threadIdx.x) >> 5;
    int lane = threadIdx.x & 31;
    if (e >= E) return;
    int   s = g_src[e];
    int   d = g_dst[e];
    float nrm = g_norm[e];
    float4 h = *reinterpret_cast<const float4*>(g_h + (size_t)s * D + lane * 4);
    float mx = h.x * nrm, my = h.y * nrm, mz = h.z * nrm, mw = h.w * nrm;
    float* p = g_out + (size_t)d * D + lane * 4;
    asm volatile("red.global.add.v4.f32 [%0], {%1, %2, %3, %4};"
                 :: "l"(p), "f"(mx), "f"(my), "f"(mz), "f"(mw) : "memory");
}

// ---------------- host launcher ----------------------------------------------
extern "C" void kernel_launch(void* const* d_in, const int* in_sizes, int n_in,
                              void* d_out, int out_size) {
    const float* x  = (const float*)d_in[0];
    const void*  ei = d_in[1];
    const float* ew = (const float*)d_in[2];
    const float* W1 = (const float*)d_in[3];
    const float* b1 = (const float*)d_in[4];
    const float* W2 = (const float*)d_in[5];
    const float* b2 = (const float*)d_in[6];
    const float* W3 = (const float*)d_in[7];
    const float* b3 = (const float*)d_in[8];
    const float* Wl = (const float*)d_in[9];
    const float* bl = (const float*)d_in[10];
    float* out = (float*)d_out;

    const int N = in_sizes[0] / D;   // 50000
    const int E = in_sizes[2];       // 800000 (edge_weights count, dtype-independent)

    float *dh = nullptr, *dout = nullptr;
    cudaGetSymbolAddress((void**)&dh,   g_h);
    cudaGetSymbolAddress((void**)&dout, g_out);

    const int T = 256;
    const int gN  = (N + T - 1) / T;
    const int gE  = (E + T - 1) / T;
    const int gG  = (N + 31) / 32;                 // gemm blocks
    const int gSB = (N * (D / 4) + T - 1) / T;     // self+bias blocks
    const int gSC = (E * 32 + T - 1) / T;          // scatter blocks (warp/edge)

    // --- gcn_norm prep ---
    k_detect   <<<1, 1>>>((const int*)ei, E);
    k_deg_init <<<gN, T>>>(N);
    k_deg_accum<<<gE, T>>>(ei, ew, E, N);
    k_dinv     <<<gN, T>>>(N);
    k_norm     <<<gE, T>>>(ew, E);

    // --- layer 1: h = x @ W1 ; out = A_norm h + b1 ---
    k_gemm<false, false><<<gG, T>>>(x, W1, nullptr, dh, N);
    k_self_bias<<<gSB, T>>>(b1, N);
    k_scatter  <<<gSC, T>>>(E);

    // --- layer 2: h = relu(out) @ W2 ---
    k_gemm<true, false><<<gG, T>>>(dout, W2, nullptr, dh, N);
    k_self_bias<<<gSB, T>>>(b2, N);
    k_scatter  <<<gSC, T>>>(E);

    // --- layer 3: h = relu(out) @ W3 ---
    k_gemm<true, false><<<gG, T>>>(dout, W3, nullptr, dh, N);
    k_self_bias<<<gSB, T>>>(b3, N);
    k_scatter  <<<gSC, T>>>(E);

    // --- final linear (no relu on layer-3 output): d_out = out @ Wl + bl ---
    k_gemm<false, true><<<gG, T>>>(dout, Wl, bl, out, N);
}

// round 3
// speedup vs baseline: 1.3960x; 1.3960x over previous
#include <cuda_runtime.h>

#define NN 50000
#define NE 800000
#define D  128
#define SCAN_B 256

// ---------------- scratch (static device globals; no allocation) -------------
__device__ float g_h  [NN * D];   // GEMM output (pre-aggregation)
__device__ float g_out[NN * D];   // aggregated output / next-layer input
__device__ float g_norm[NE];
__device__ int   g_src [NE];
__device__ int   g_dst [NE];
__device__ float g_deg [NN];
__device__ float g_dinv[NN];
__device__ int   g_is64;          // 1 if edge_index is int64, 0 if int32
// CSR (by dst)
__device__ int   g_cnt   [NN];
__device__ int   g_rowtmp[NN];
__device__ int   g_rowptr[NN + 1];
__device__ int   g_ofs   [NN];
__device__ int   g_bsum  [SCAN_B];
__device__ int   g_boff  [SCAN_B];
__device__ int2  g_csr   [NE];    // .x = src, .y = bitcast(norm)

// ---------------- packed f32x2 helpers (Blackwell) ---------------------------
__device__ __forceinline__ unsigned long long pk2(float lo, float hi) {
    unsigned long long r;
    asm("mov.b64 %0, {%1, %2};" : "=l"(r) : "f"(lo), "f"(hi));
    return r;
}
__device__ __forceinline__ void fma2(unsigned long long& d,
                                     unsigned long long a,
                                     unsigned long long b) {
    asm("fma.rn.f32x2 %0, %1, %2, %0;" : "+l"(d) : "l"(a), "l"(b));
}
__device__ __forceinline__ float2 up2(unsigned long long v) {
    float2 f;
    asm("mov.b64 {%0, %1}, %2;" : "=f"(f.x), "=f"(f.y) : "l"(v));
    return f;
}

// ---------------- edge-index dtype detection ----------------------------------
__global__ void k_detect(const int* __restrict__ ei32, int E) {
    int odd_zero = 1;
    for (int i = 0; i < 64; i++) {
        if (ei32[2 * i + 1] != 0) { odd_zero = 0; break; }
    }
    g_is64 = odd_zero;
}

// ---------------- degree / norm prep -----------------------------------------
__global__ void k_deg_init(int n) {
    int i = blockIdx.x * blockDim.x + threadIdx.x;
    if (i < n) { g_deg[i] = 1.0f; g_cnt[i] = 0; }
}

__global__ void k_deg_accum(const void* __restrict__ ei_raw,
                            const float* __restrict__ w, int E, int n) {
    int e = blockIdx.x * blockDim.x + threadIdx.x;
    if (e >= E) return;
    int s, d;
    if (g_is64) {
        const long long* ei = (const long long*)ei_raw;
        s = (int)ei[e];
        d = (int)ei[E + e];
    } else {
        const int* ei = (const int*)ei_raw;
        s = ei[e];
        d = ei[E + e];
    }
    if ((unsigned)s >= (unsigned)n) s = 0;
    if ((unsigned)d >= (unsigned)n) d = 0;
    g_src[e] = s;
    g_dst[e] = d;
    atomicAdd(&g_deg[d], w[e]);
    atomicAdd(&g_cnt[d], 1);
}

__global__ void k_dinv(int n) {
    int i = blockIdx.x * blockDim.x + threadIdx.x;
    if (i < n) g_dinv[i] = rsqrtf(g_deg[i]);
}

__global__ void k_norm(const float* __restrict__ w, int E) {
    int e = blockIdx.x * blockDim.x + threadIdx.x;
    if (e < E) g_norm[e] = g_dinv[g_src[e]] * w[e] * g_dinv[g_dst[e]];
}

// ---------------- CSR build: 3-kernel exclusive scan + fill -------------------
__global__ void k_scan1(int n) {              // grid = ceil(n/SCAN_B)
    __shared__ int sh[SCAN_B];
    int i = blockIdx.x * SCAN_B + threadIdx.x;
    int v = (i < n) ? g_cnt[i] : 0;
    sh[threadIdx.x] = v;
    __syncthreads();
    for (int o = 1; o < SCAN_B; o <<= 1) {
        int t = (threadIdx.x >= o) ? sh[threadIdx.x - o] : 0;
        __syncthreads();
        sh[threadIdx.x] += t;
        __syncthreads();
    }
    if (i < n) g_rowtmp[i] = sh[threadIdx.x] - v;   // exclusive within block
    if (threadIdx.x == SCAN_B - 1) g_bsum[blockIdx.x] = sh[SCAN_B - 1];
}

__global__ void k_scan2(int nb) {             // 1 block
    __shared__ int sh[SCAN_B];
    int v = (threadIdx.x < nb) ? g_bsum[threadIdx.x] : 0;
    sh[threadIdx.x] = v;
    __syncthreads();
    for (int o = 1; o < SCAN_B; o <<= 1) {
        int t = (threadIdx.x >= o) ? sh[threadIdx.x - o] : 0;
        __syncthreads();
        sh[threadIdx.x] += t;
        __syncthreads();
    }
    g_boff[threadIdx.x] = sh[threadIdx.x] - v;      // exclusive block offsets
}

__global__ void k_scan3(int n, int E) {
    int i = blockIdx.x * blockDim.x + threadIdx.x;
    if (i < n) {
        int r = g_rowtmp[i] + g_boff[i / SCAN_B];
        g_rowptr[i] = r;
        g_ofs[i]    = r;
    }
    if (i == 0) g_rowptr[n] = E;
}

__global__ void k_fill(int E) {
    int e = blockIdx.x * blockDim.x + threadIdx.x;
    if (e >= E) return;
    int d   = g_dst[e];
    int pos = atomicAdd(&g_ofs[d], 1);
    int2 v;
    v.x = g_src[e];
    v.y = __float_as_int(g_norm[e]);
    g_csr[pos] = v;
}

// ---------------- GEMM: out[r][c] = act(in[r]) . W[:,c] (+bias) --------------
template <bool RELU, bool BIAS>
__global__ void __launch_bounds__(256)
k_gemm(const float* __restrict__ in, const float* __restrict__ W,
       const float* __restrict__ bias, float* __restrict__ out, int n) {
    const int tx = threadIdx.x & 31;
    const int ty = threadIdx.x >> 5;
    const int c0 = tx * 4;
    const int r0 = blockIdx.x * 32 + ty * 4;

    unsigned long long acc[4][2];
#pragma unroll
    for (int i = 0; i < 4; i++) { acc[i][0] = 0ull; acc[i][1] = 0ull; }

    for (int k = 0; k < D; k += 4) {
        float4 xv[4];
#pragma unroll
        for (int i = 0; i < 4; i++) {
            int r = r0 + i;
            if (r < n) {
                xv[i] = *reinterpret_cast<const float4*>(in + (size_t)r * D + k);
                if (RELU) {
                    xv[i].x = fmaxf(xv[i].x, 0.0f);
                    xv[i].y = fmaxf(xv[i].y, 0.0f);
                    xv[i].z = fmaxf(xv[i].z, 0.0f);
                    xv[i].w = fmaxf(xv[i].w, 0.0f);
                }
            } else {
                xv[i] = make_float4(0.f, 0.f, 0.f, 0.f);
            }
        }
#pragma unroll
        for (int kk = 0; kk < 4; kk++) {
            float4 wv = *reinterpret_cast<const float4*>(W + (size_t)(k + kk) * D + c0);
            unsigned long long b01 = pk2(wv.x, wv.y);
            unsigned long long b23 = pk2(wv.z, wv.w);
#pragma unroll
            for (int i = 0; i < 4; i++) {
                float a = (kk == 0) ? xv[i].x : (kk == 1) ? xv[i].y
                        : (kk == 2) ? xv[i].z : xv[i].w;
                unsigned long long a2 = pk2(a, a);
                fma2(acc[i][0], a2, b01);
                fma2(acc[i][1], a2, b23);
            }
        }
    }

#pragma unroll
    for (int i = 0; i < 4; i++) {
        int r = r0 + i;
        if (r >= n) continue;
        float2 p0 = up2(acc[i][0]);
        float2 p1 = up2(acc[i][1]);
        float4 o = make_float4(p0.x, p0.y, p1.x, p1.y);
        if (BIAS) {
            o.x += bias[c0 + 0];
            o.y += bias[c0 + 1];
            o.z += bias[c0 + 2];
            o.w += bias[c0 + 3];
        }
        *reinterpret_cast<float4*>(out + (size_t)r * D + c0) = o;
    }
}

// ---------------- fused aggregation: out[i] = h[i]/deg + b + sum h[src]*nrm ---
// one warp per node; lane owns a float4 column chunk; no atomics.
__global__ void __launch_bounds__(256)
k_agg(const float* __restrict__ bias, int n) {
    int node = (blockIdx.x * blockDim.x + threadIdx.x) >> 5;
    int lane = threadIdx.x & 31;
    if (node >= n) return;

    int beg = g_rowptr[node];
    int end = g_rowptr[node + 1];
    float di = g_dinv[node];
    float s  = di * di;                       // self-loop norm = 1/deg

    float4 hv = *reinterpret_cast<const float4*>(g_h + (size_t)node * D + lane * 4);
    float4 bv = *reinterpret_cast<const float4*>(bias + lane * 4);
    float ax = fmaf(hv.x, s, bv.x);
    float ay = fmaf(hv.y, s, bv.y);
    float az = fmaf(hv.z, s, bv.z);
    float aw = fmaf(hv.w, s, bv.w);

    int e = beg;
    // unroll-by-2 for load overlap
    for (; e + 1 < end; e += 2) {
        int2 c0 = g_csr[e];
        int2 c1 = g_csr[e + 1];
        float n0 = __int_as_float(c0.y);
        float n1 = __int_as_float(c1.y);
        float4 h0 = *reinterpret_cast<const float4*>(g_h + (size_t)c0.x * D + lane * 4);
        float4 h1 = *reinterpret_cast<const float4*>(g_h + (size_t)c1.x * D + lane * 4);
        ax = fmaf(h0.x, n0, ax); ay = fmaf(h0.y, n0, ay);
        az = fmaf(h0.z, n0, az); aw = fmaf(h0.w, n0, aw);
        ax = fmaf(h1.x, n1, ax); ay = fmaf(h1.y, n1, ay);
        az = fmaf(h1.z, n1, az); aw = fmaf(h1.w, n1, aw);
    }
    if (e < end) {
        int2 c0 = g_csr[e];
        float n0 = __int_as_float(c0.y);
        float4 h0 = *reinterpret_cast<const float4*>(g_h + (size_t)c0.x * D + lane * 4);
        ax = fmaf(h0.x, n0, ax); ay = fmaf(h0.y, n0, ay);
        az = fmaf(h0.z, n0, az); aw = fmaf(h0.w, n0, aw);
    }

    float4 o = make_float4(ax, ay, az, aw);
    *reinterpret_cast<float4*>(g_out + (size_t)node * D + lane * 4) = o;
}

// ---------------- host launcher ----------------------------------------------
extern "C" void kernel_launch(void* const* d_in, const int* in_sizes, int n_in,
                              void* d_out, int out_size) {
    const float* x  = (const float*)d_in[0];
    const void*  ei = d_in[1];
    const float* ew = (const float*)d_in[2];
    const float* W1 = (const float*)d_in[3];
    const float* b1 = (const float*)d_in[4];
    const float* W2 = (const float*)d_in[5];
    const float* b2 = (const float*)d_in[6];
    const float* W3 = (const float*)d_in[7];
    const float* b3 = (const float*)d_in[8];
    const float* Wl = (const float*)d_in[9];
    const float* bl = (const float*)d_in[10];
    float* out = (float*)d_out;

    const int N = in_sizes[0] / D;   // 50000
    const int E = in_sizes[2];       // 800000

    float *dh = nullptr, *dout = nullptr;
    cudaGetSymbolAddress((void**)&dh,   g_h);
    cudaGetSymbolAddress((void**)&dout, g_out);

    const int T = 256;
    const int gN  = (N + T - 1) / T;
    const int gE  = (E + T - 1) / T;
    const int gG  = (N + 31) / 32;             // gemm blocks
    const int gA  = (N * 32 + T - 1) / T;      // agg blocks (warp/node)
    const int nb  = (N + SCAN_B - 1) / SCAN_B; // scan blocks (196 <= 256)

    // --- gcn_norm prep + CSR build ---
    k_detect   <<<1, 1>>>((const int*)ei, E);
    k_deg_init <<<gN, T>>>(N);
    k_deg_accum<<<gE, T>>>(ei, ew, E, N);
    k_dinv     <<<gN, T>>>(N);
    k_norm     <<<gE, T>>>(ew, E);
    k_scan1    <<<nb, SCAN_B>>>(N);
    k_scan2    <<<1,  SCAN_B>>>(nb);
    k_scan3    <<<gN, T>>>(N, E);
    k_fill     <<<gE, T>>>(E);

    // --- layer 1 ---
    k_gemm<false, false><<<gG, T>>>(x, W1, nullptr, dh, N);
    k_agg<<<gA, T>>>(b1, N);
    // --- layer 2 ---
    k_gemm<true, false><<<gG, T>>>(dout, W2, nullptr, dh, N);
    k_agg<<<gA, T>>>(b2, N);
    // --- layer 3 ---
    k_gemm<true, false><<<gG, T>>>(dout, W3, nullptr, dh, N);
    k_agg<<<gA, T>>>(b3, N);
    // --- final linear ---
    k_gemm<false, true><<<gG, T>>>(dout, Wl, bl, out, N);
}

// round 6
// speedup vs baseline: 2.0488x; 1.4676x over previous
#include <cuda_runtime.h>
#include <cuda_bf16.h>
#include <cstdint>

#define NN 50000
#define NE 800000
#define D  128
#define SCAN_B 256
#define TM 128

// bf16 tile row stride: 64 data bf16 (128B) + 16B pad = 144B (conflict-free ldmatrix)
#define LDS_STRIDE_B 144
// smem tile offsets (bytes): 128 rows * 144B = 18432 each
#define AHI_OFF 0
#define ALO_OFF 18432
#define BHI_OFF 36864
#define BLO_OFF 55296
#define SM_TOTAL 73728

// ---------------- scratch (static device globals; no allocation) -------------
__device__ float g_h  [NN * D];
__device__ float g_out[NN * D];
__device__ float g_norm[NE];
__device__ int   g_src [NE];
__device__ int   g_dst [NE];
__device__ float g_deg [NN];
__device__ float g_dinv[NN];
__device__ int   g_is64;
// CSR (by dst)
__device__ int   g_cnt   [NN];
__device__ int   g_rowtmp[NN];
__device__ int   g_rowptr[NN + 1];
__device__ int   g_ofs   [NN];
__device__ int   g_bsum  [SCAN_B];
__device__ int   g_boff  [SCAN_B];
__device__ int2  g_csr   [NE];

// ---------------- helpers ------------------------------------------------------
__device__ __forceinline__ uint32_t smem_u32(const void* p) {
    uint32_t a;
    asm("{ .reg .u64 t; cvta.to.shared.u64 t, %1; cvt.u32.u64 %0, t; }" : "=r"(a) : "l"(p));
    return a;
}

__device__ __forceinline__ void ldmx4(uint32_t& r0, uint32_t& r1, uint32_t& r2,
                                      uint32_t& r3, uint32_t addr) {
    asm volatile("ldmatrix.sync.aligned.m8n8.x4.shared.b16 {%0,%1,%2,%3}, [%4];"
                 : "=r"(r0), "=r"(r1), "=r"(r2), "=r"(r3) : "r"(addr));
}

__device__ __forceinline__ void mma_bf16(float& c0, float& c1, float& c2, float& c3,
                                         uint32_t a0, uint32_t a1, uint32_t a2, uint32_t a3,
                                         uint32_t b0, uint32_t b1) {
    asm volatile("mma.sync.aligned.m16n8k16.row.col.f32.bf16.bf16.f32 "
                 "{%0,%1,%2,%3}, {%4,%5,%6,%7}, {%8,%9}, {%0,%1,%2,%3};"
                 : "+f"(c0), "+f"(c1), "+f"(c2), "+f"(c3)
                 : "r"(a0), "r"(a1), "r"(a2), "r"(a3), "r"(b0), "r"(b1));
}

// split a float into bf16 hi + bf16 lo, packed pairwise
__device__ __forceinline__ void split2(float x, float y, uint32_t& hi, uint32_t& lo) {
    __nv_bfloat16 hx = __float2bfloat16(x), hy = __float2bfloat16(y);
    __nv_bfloat16 lx = __float2bfloat16(x - __bfloat162float(hx));
    __nv_bfloat16 ly = __float2bfloat16(y - __bfloat162float(hy));
    hi = (uint32_t)__bfloat16_as_ushort(hx) | ((uint32_t)__bfloat16_as_ushort(hy) << 16);
    lo = (uint32_t)__bfloat16_as_ushort(lx) | ((uint32_t)__bfloat16_as_ushort(ly) << 16);
}

// ---------------- tensor-core GEMM: out = act(in) @ W (+bias) ----------------
// grid = ceil(n/128), block = 256 (8 warps). Split-bf16 fp32 emulation via mma.sync.
// Two K-stages of 64 columns each; A/B hi/lo tiles are 128x64 bf16 in smem.
template <bool RELU, bool BIAS>
__global__ void __launch_bounds__(256)
k_tgemm(const float* __restrict__ in, const float* __restrict__ W,
        const float* __restrict__ bias, float* __restrict__ out, int n) {
    extern __shared__ char smem[];
    const uint32_t sb  = smem_u32(smem);
    const int tid   = threadIdx.x;
    const int wid   = tid >> 5;
    const int lane  = tid & 31;
    const int rbase = blockIdx.x * TM;

    // ldmatrix lane address components (fixed across stages)
    const int m0 = wid * 16;
    const int rowInA = (lane & 7) + ((lane >> 3) & 1) * 8;     // 0..15
    const int kAddA  = (lane >> 4) * 8;                        // 0 or 8
    const uint32_t aOffBytes = (uint32_t)((m0 + rowInA) * LDS_STRIDE_B + kAddA * 2);
    const int rowInB = (lane & 7) + (lane >> 4) * 8;           // n offset 0..15
    const int kAddB  = ((lane >> 3) & 1) * 8;                  // 0 or 8
    const uint32_t bOffBytes = (uint32_t)(rowInB * LDS_STRIDE_B + kAddB * 2);

    float acc[16][4];
#pragma unroll
    for (int t = 0; t < 16; t++) {
        acc[t][0] = 0.f; acc[t][1] = 0.f; acc[t][2] = 0.f; acc[t][3] = 0.f;
    }

    const int fillRow = tid >> 1;          // 0..127 (row for A, n-index for B)
    const int fillSub = (tid & 1) * 32;    // which 32-col half of the 64-col stage

#pragma unroll
    for (int stage = 0; stage < 2; stage++) {
        const int kstage = stage * 64;

        // ---- A fill: 32 cols = 8 float4 loads ----
        {
            const int r = rbase + fillRow;
            const float4* src = (const float4*)(in + (size_t)r * D + kstage + fillSub);
            char* ah = smem + AHI_OFF + fillRow * LDS_STRIDE_B + fillSub * 2;
            char* al = smem + ALO_OFF + fillRow * LDS_STRIDE_B + fillSub * 2;
#pragma unroll
            for (int k4 = 0; k4 < 8; k4++) {
                float4 v = (r < n) ? src[k4] : make_float4(0.f, 0.f, 0.f, 0.f);
                if (RELU) {
                    v.x = fmaxf(v.x, 0.f); v.y = fmaxf(v.y, 0.f);
                    v.z = fmaxf(v.z, 0.f); v.w = fmaxf(v.w, 0.f);
                }
                uint32_t h01, l01, h23, l23;
                split2(v.x, v.y, h01, l01);
                split2(v.z, v.w, h23, l23);
                *(uint32_t*)(ah + k4 * 8)     = h01;
                *(uint32_t*)(ah + k4 * 8 + 4) = h23;
                *(uint32_t*)(al + k4 * 8)     = l01;
                *(uint32_t*)(al + k4 * 8 + 4) = l23;
            }
        }
        // ---- B fill: B[nn][klocal] = W[kstage+klocal][nn], 32 k values ----
        {
            const int nn = fillRow;
            char* bh = smem + BHI_OFF + nn * LDS_STRIDE_B + fillSub * 2;
            char* bl = smem + BLO_OFF + nn * LDS_STRIDE_B + fillSub * 2;
#pragma unroll
            for (int k = 0; k < 32; k += 2) {
                float w0 = W[(size_t)(kstage + fillSub + k) * D + nn];
                float w1 = W[(size_t)(kstage + fillSub + k + 1) * D + nn];
                uint32_t hi, lo;
                split2(w0, w1, hi, lo);
                *(uint32_t*)(bh + k * 2) = hi;
                *(uint32_t*)(bl + k * 2) = lo;
            }
        }
        __syncthreads();

        // ---- mma over this stage's 64 K columns (4 sub-steps of 16) ----
#pragma unroll
        for (int ks = 0; ks < 4; ks++) {
            const uint32_t kb = (uint32_t)(ks * 32);   // 16 bf16 = 32 bytes
            uint32_t ah0, ah1, ah2, ah3, al0, al1, al2, al3;
            ldmx4(ah0, ah1, ah2, ah3, sb + AHI_OFF + aOffBytes + kb);
            ldmx4(al0, al1, al2, al3, sb + ALO_OFF + aOffBytes + kb);
#pragma unroll
            for (int nc = 0; nc < 8; nc++) {
                const uint32_t bAddr = bOffBytes + (uint32_t)(nc * 16 * LDS_STRIDE_B) + kb;
                uint32_t bh0, bh1, bh2, bh3, bl0, bl1, bl2, bl3;
                ldmx4(bh0, bh1, bh2, bh3, sb + BHI_OFF + bAddr);
                ldmx4(bl0, bl1, bl2, bl3, sb + BLO_OFF + bAddr);
                float* c0 = acc[nc * 2];
                float* c1 = acc[nc * 2 + 1];
                mma_bf16(c0[0], c0[1], c0[2], c0[3], ah0, ah1, ah2, ah3, bh0, bh1);
                mma_bf16(c0[0], c0[1], c0[2], c0[3], ah0, ah1, ah2, ah3, bl0, bl1);
                mma_bf16(c0[0], c0[1], c0[2], c0[3], al0, al1, al2, al3, bh0, bh1);
                mma_bf16(c1[0], c1[1], c1[2], c1[3], ah0, ah1, ah2, ah3, bh2, bh3);
                mma_bf16(c1[0], c1[1], c1[2], c1[3], ah0, ah1, ah2, ah3, bl2, bl3);
                mma_bf16(c1[0], c1[1], c1[2], c1[3], al0, al1, al2, al3, bh2, bh3);
            }
        }
        __syncthreads();   // before buffers are overwritten by next stage
    }

    // ---- epilogue ----
    const int rTop = rbase + m0 + (lane >> 2);   // rows rTop and rTop+8
    const int cOff = (lane & 3) * 2;
#pragma unroll
    for (int t = 0; t < 16; t++) {
        const int col = t * 8 + cOff;
        float bx = 0.f, by = 0.f;
        if (BIAS) { bx = bias[col]; by = bias[col + 1]; }
        if (rTop < n) {
            float2 v = make_float2(acc[t][0] + bx, acc[t][1] + by);
            *(float2*)(out + (size_t)rTop * D + col) = v;
        }
        if (rTop + 8 < n) {
            float2 v = make_float2(acc[t][2] + bx, acc[t][3] + by);
            *(float2*)(out + (size_t)(rTop + 8) * D + col) = v;
        }
    }
}

// ---------------- edge-index dtype detection ----------------------------------
__global__ void k_detect(const int* __restrict__ ei32, int E) {
    int odd_zero = 1;
    for (int i = 0; i < 64; i++) if (ei32[2 * i + 1] != 0) { odd_zero = 0; break; }
    g_is64 = odd_zero;
}

// ---------------- degree / norm prep -----------------------------------------
__global__ void k_deg_init(int n) {
    int i = blockIdx.x * blockDim.x + threadIdx.x;
    if (i < n) { g_deg[i] = 1.0f; g_cnt[i] = 0; }
}

__global__ void k_deg_accum(const void* __restrict__ ei_raw,
                            const float* __restrict__ w, int E, int n) {
    int e = blockIdx.x * blockDim.x + threadIdx.x;
    if (e >= E) return;
    int s, d;
    if (g_is64) {
        const long long* ei = (const long long*)ei_raw;
        s = (int)ei[e]; d = (int)ei[E + e];
    } else {
        const int* ei = (const int*)ei_raw;
        s = ei[e]; d = ei[E + e];
    }
    if ((unsigned)s >= (unsigned)n) s = 0;
    if ((unsigned)d >= (unsigned)n) d = 0;
    g_src[e] = s; g_dst[e] = d;
    atomicAdd(&g_deg[d], w[e]);
    atomicAdd(&g_cnt[d], 1);
}

__global__ void k_dinv(int n) {
    int i = blockIdx.x * blockDim.x + threadIdx.x;
    if (i < n) g_dinv[i] = rsqrtf(g_deg[i]);
}

__global__ void k_norm(const float* __restrict__ w, int E) {
    int e = blockIdx.x * blockDim.x + threadIdx.x;
    if (e < E) g_norm[e] = g_dinv[g_src[e]] * w[e] * g_dinv[g_dst[e]];
}

// ---------------- CSR build ----------------------------------------------------
__global__ void k_scan1(int n) {
    __shared__ int sh[SCAN_B];
    int i = blockIdx.x * SCAN_B + threadIdx.x;
    int v = (i < n) ? g_cnt[i] : 0;
    sh[threadIdx.x] = v;
    __syncthreads();
    for (int o = 1; o < SCAN_B; o <<= 1) {
        int t = (threadIdx.x >= o) ? sh[threadIdx.x - o] : 0;
        __syncthreads();
        sh[threadIdx.x] += t;
        __syncthreads();
    }
    if (i < n) g_rowtmp[i] = sh[threadIdx.x] - v;
    if (threadIdx.x == SCAN_B - 1) g_bsum[blockIdx.x] = sh[SCAN_B - 1];
}

__global__ void k_scan2(int nb) {
    __shared__ int sh[SCAN_B];
    int v = (threadIdx.x < nb) ? g_bsum[threadIdx.x] : 0;
    sh[threadIdx.x] = v;
    __syncthreads();
    for (int o = 1; o < SCAN_B; o <<= 1) {
        int t = (threadIdx.x >= o) ? sh[threadIdx.x - o] : 0;
        __syncthreads();
        sh[threadIdx.x] += t;
        __syncthreads();
    }
    g_boff[threadIdx.x] = sh[threadIdx.x] - v;
}

__global__ void k_scan3(int n, int E) {
    int i = blockIdx.x * blockDim.x + threadIdx.x;
    if (i < n) {
        int r = g_rowtmp[i] + g_boff[i / SCAN_B];
        g_rowptr[i] = r;
        g_ofs[i]    = r;
    }
    if (i == 0) g_rowptr[n] = E;
}

__global__ void k_fill(int E) {
    int e = blockIdx.x * blockDim.x + threadIdx.x;
    if (e >= E) return;
    int d   = g_dst[e];
    int pos = atomicAdd(&g_ofs[d], 1);
    int2 v;
    v.x = g_src[e];
    v.y = __float_as_int(g_norm[e]);
    g_csr[pos] = v;
}

// ---------------- fused aggregation (gather, no atomics) ----------------------
__global__ void __launch_bounds__(256)
k_agg(const float* __restrict__ bias, int n) {
    int node = (blockIdx.x * blockDim.x + threadIdx.x) >> 5;
    int lane = threadIdx.x & 31;
    if (node >= n) return;

    int beg = g_rowptr[node];
    int end = g_rowptr[node + 1];
    float di = g_dinv[node];
    float s  = di * di;

    float4 hv = *(const float4*)(g_h + (size_t)node * D + lane * 4);
    float4 bv = *(const float4*)(bias + lane * 4);
    float ax = fmaf(hv.x, s, bv.x);
    float ay = fmaf(hv.y, s, bv.y);
    float az = fmaf(hv.z, s, bv.z);
    float aw = fmaf(hv.w, s, bv.w);

    int e = beg;
    for (; e + 1 < end; e += 2) {
        int2 c0 = g_csr[e];
        int2 c1 = g_csr[e + 1];
        float n0 = __int_as_float(c0.y);
        float n1 = __int_as_float(c1.y);
        float4 h0 = *(const float4*)(g_h + (size_t)c0.x * D + lane * 4);
        float4 h1 = *(const float4*)(g_h + (size_t)c1.x * D + lane * 4);
        ax = fmaf(h0.x, n0, ax); ay = fmaf(h0.y, n0, ay);
        az = fmaf(h0.z, n0, az); aw = fmaf(h0.w, n0, aw);
        ax = fmaf(h1.x, n1, ax); ay = fmaf(h1.y, n1, ay);
        az = fmaf(h1.z, n1, az); aw = fmaf(h1.w, n1, aw);
    }
    if (e < end) {
        int2 c0 = g_csr[e];
        float n0 = __int_as_float(c0.y);
        float4 h0 = *(const float4*)(g_h + (size_t)c0.x * D + lane * 4);
        ax = fmaf(h0.x, n0, ax); ay = fmaf(h0.y, n0, ay);
        az = fmaf(h0.z, n0, az); aw = fmaf(h0.w, n0, aw);
    }
    *(float4*)(g_out + (size_t)node * D + lane * 4) = make_float4(ax, ay, az, aw);
}

// ---------------- host launcher ----------------------------------------------
extern "C" void kernel_launch(void* const* d_in, const int* in_sizes, int n_in,
                              void* d_out, int out_size) {
    const float* x  = (const float*)d_in[0];
    const void*  ei = d_in[1];
    const float* ew = (const float*)d_in[2];
    const float* W1 = (const float*)d_in[3];
    const float* b1 = (const float*)d_in[4];
    const float* W2 = (const float*)d_in[5];
    const float* b2 = (const float*)d_in[6];
    const float* W3 = (const float*)d_in[7];
    const float* b3 = (const float*)d_in[8];
    const float* Wl = (const float*)d_in[9];
    const float* bl = (const float*)d_in[10];
    float* out = (float*)d_out;

    const int N = in_sizes[0] / D;
    const int E = in_sizes[2];

    float *dh = nullptr, *dout = nullptr;
    cudaGetSymbolAddress((void**)&dh,   g_h);
    cudaGetSymbolAddress((void**)&dout, g_out);

    cudaFuncSetAttribute(k_tgemm<false, false>, cudaFuncAttributeMaxDynamicSharedMemorySize, SM_TOTAL);
    cudaFuncSetAttribute(k_tgemm<true,  false>, cudaFuncAttributeMaxDynamicSharedMemorySize, SM_TOTAL);
    cudaFuncSetAttribute(k_tgemm<false, true>,  cudaFuncAttributeMaxDynamicSharedMemorySize, SM_TOTAL);

    const int T = 256;
    const int gN = (N + T - 1) / T;
    const int gE = (E + T - 1) / T;
    const int gG = (N + TM - 1) / TM;
    const int gA = (N * 32 + T - 1) / T;
    const int nb = (N + SCAN_B - 1) / SCAN_B;

    // --- gcn_norm prep + CSR build ---
    k_detect   <<<1, 1>>>((const int*)ei, E);
    k_deg_init <<<gN, T>>>(N);
    k_deg_accum<<<gE, T>>>(ei, ew, E, N);
    k_dinv     <<<gN, T>>>(N);
    k_norm     <<<gE, T>>>(ew, E);
    k_scan1    <<<nb, SCAN_B>>>(N);
    k_scan2    <<<1,  SCAN_B>>>(nb);
    k_scan3    <<<gN, T>>>(N, E);
    k_fill     <<<gE, T>>>(E);

    // --- layer 1 ---
    k_tgemm<false, false><<<gG, T, SM_TOTAL>>>(x, W1, nullptr, dh, N);
    k_agg<<<gA, T>>>(b1, N);
    // --- layer 2 ---
    k_tgemm<true, false><<<gG, T, SM_TOTAL>>>(dout, W2, nullptr, dh, N);
    k_agg<<<gA, T>>>(b2, N);
    // --- layer 3 ---
    k_tgemm<true, false><<<gG, T, SM_TOTAL>>>(dout, W3, nullptr, dh, N);
    k_agg<<<gA, T>>>(b3, N);
    // --- final linear ---
    k_tgemm<false, true><<<gG, T, SM_TOTAL>>>(dout, Wl, bl, out, N);
}

// round 7
// speedup vs baseline: 2.1287x; 1.0390x over previous
#include <cuda_runtime.h>
#include <cuda_bf16.h>
#include <cstdint>

#define NN 50000
#define NE 800000
#define D  128
#define SCAN_B 256
#define TM 128

// bf16 tile row stride: 64 data bf16 (128B) + 16B pad = 144B (conflict-free ldmatrix)
#define LDS_STRIDE_B 144
#define AHI_OFF 0
#define ALO_OFF 18432
#define BHI_OFF 36864
#define BLO_OFF 55296
#define SM_TOTAL 73728

// ---------------- scratch (static device globals; no allocation) -------------
__device__ float g_h  [NN * D];
__device__ float g_out[NN * D];
__device__ int   g_src [NE];
__device__ int   g_dst [NE];
__device__ float g_deg [NN];
__device__ float g_dinv[NN];
__device__ int   g_is64;
// CSR (by dst)
__device__ int   g_cnt   [NN];
__device__ int   g_rowtmp[NN];
__device__ int   g_rowptr[NN + 1];
__device__ int   g_ofs   [NN];
__device__ int   g_bsum  [SCAN_B];
__device__ int   g_boff  [SCAN_B];
__device__ int2  g_csr   [NE];    // .x = src, .y = bitcast(norm)
// pre-split transposed weights: [w][nn][k] bf16, 4 * 128 * 128
__device__ unsigned short g_whi[4 * 16384];
__device__ unsigned short g_wlo[4 * 16384];

// ---------------- helpers ------------------------------------------------------
__device__ __forceinline__ uint32_t smem_u32(const void* p) {
    uint32_t a;
    asm("{ .reg .u64 t; cvta.to.shared.u64 t, %1; cvt.u32.u64 %0, t; }" : "=r"(a) : "l"(p));
    return a;
}

__device__ __forceinline__ void ldmx4(uint32_t& r0, uint32_t& r1, uint32_t& r2,
                                      uint32_t& r3, uint32_t addr) {
    asm volatile("ldmatrix.sync.aligned.m8n8.x4.shared.b16 {%0,%1,%2,%3}, [%4];"
                 : "=r"(r0), "=r"(r1), "=r"(r2), "=r"(r3) : "r"(addr));
}

__device__ __forceinline__ void mma_bf16(float& c0, float& c1, float& c2, float& c3,
                                         uint32_t a0, uint32_t a1, uint32_t a2, uint32_t a3,
                                         uint32_t b0, uint32_t b1) {
    asm volatile("mma.sync.aligned.m16n8k16.row.col.f32.bf16.bf16.f32 "
                 "{%0,%1,%2,%3}, {%4,%5,%6,%7}, {%8,%9}, {%0,%1,%2,%3};"
                 : "+f"(c0), "+f"(c1), "+f"(c2), "+f"(c3)
                 : "r"(a0), "r"(a1), "r"(a2), "r"(a3), "r"(b0), "r"(b1));
}

__device__ __forceinline__ void split2(float x, float y, uint32_t& hi, uint32_t& lo) {
    __nv_bfloat16 hx = __float2bfloat16(x), hy = __float2bfloat16(y);
    __nv_bfloat16 lx = __float2bfloat16(x - __bfloat162float(hx));
    __nv_bfloat16 ly = __float2bfloat16(y - __bfloat162float(hy));
    hi = (uint32_t)__bfloat16_as_ushort(hx) | ((uint32_t)__bfloat16_as_ushort(hy) << 16);
    lo = (uint32_t)__bfloat16_as_ushort(lx) | ((uint32_t)__bfloat16_as_ushort(ly) << 16);
}

// ---------------- weight pre-split (transpose + bf16 hi/lo) -------------------
// grid: 4 weights * 4 ktiles * 4 ntiles = 64 blocks of (32, 8)
__global__ void k_wsplit(const float* __restrict__ W0, const float* __restrict__ W1,
                         const float* __restrict__ W2, const float* __restrict__ W3) {
    __shared__ float tile[32][33];
    const int b  = blockIdx.x;
    const int w  = b >> 4;
    const int k0 = ((b >> 2) & 3) * 32;
    const int n0 = (b & 3) * 32;
    const float* W = (w == 0) ? W0 : (w == 1) ? W1 : (w == 2) ? W2 : W3;
    const int tx = threadIdx.x, ty = threadIdx.y;
#pragma unroll
    for (int i = 0; i < 4; i++)
        tile[ty + 8 * i][tx] = W[(size_t)(k0 + ty + 8 * i) * D + n0 + tx];
    __syncthreads();
#pragma unroll
    for (int i = 0; i < 4; i++) {
        // out[nn][k] = W[k][nn]; nn = n0+ty+8i, k = k0+tx
        float v = tile[tx][ty + 8 * i];
        __nv_bfloat16 h = __float2bfloat16(v);
        __nv_bfloat16 l = __float2bfloat16(v - __bfloat162float(h));
        size_t idx = (size_t)w * 16384 + (size_t)(n0 + ty + 8 * i) * D + k0 + tx;
        g_whi[idx] = __bfloat16_as_ushort(h);
        g_wlo[idx] = __bfloat16_as_ushort(l);
    }
}

// ---------------- tensor-core GEMM: out = act(in) @ W (+bias) ----------------
template <bool RELU, bool BIAS>
__global__ void __launch_bounds__(256)
k_tgemm(const float* __restrict__ in, const unsigned short* __restrict__ whi,
        const unsigned short* __restrict__ wlo,
        const float* __restrict__ bias, float* __restrict__ out, int n) {
    extern __shared__ char smem[];
    const uint32_t sb  = smem_u32(smem);
    const int tid   = threadIdx.x;
    const int wid   = tid >> 5;
    const int lane  = tid & 31;
    const int rbase = blockIdx.x * TM;

    const int m0 = wid * 16;
    const int rowInA = (lane & 7) + ((lane >> 3) & 1) * 8;
    const int kAddA  = (lane >> 4) * 8;
    const uint32_t aOffBytes = (uint32_t)((m0 + rowInA) * LDS_STRIDE_B + kAddA * 2);
    const int rowInB = (lane & 7) + (lane >> 4) * 8;
    const int kAddB  = ((lane >> 3) & 1) * 8;
    const uint32_t bOffBytes = (uint32_t)(rowInB * LDS_STRIDE_B + kAddB * 2);

    float acc[16][4];
#pragma unroll
    for (int t = 0; t < 16; t++) {
        acc[t][0] = 0.f; acc[t][1] = 0.f; acc[t][2] = 0.f; acc[t][3] = 0.f;
    }

    const int fillRow = tid >> 1;
    const int fillSub = (tid & 1) * 32;

#pragma unroll
    for (int stage = 0; stage < 2; stage++) {
        const int kstage = stage * 64;

        // ---- A fill: convert 32 fp32 -> bf16 hi/lo ----
        {
            const int r = rbase + fillRow;
            const float4* src = (const float4*)(in + (size_t)r * D + kstage + fillSub);
            char* ah = smem + AHI_OFF + fillRow * LDS_STRIDE_B + fillSub * 2;
            char* al = smem + ALO_OFF + fillRow * LDS_STRIDE_B + fillSub * 2;
#pragma unroll
            for (int k4 = 0; k4 < 8; k4++) {
                float4 v = (r < n) ? src[k4] : make_float4(0.f, 0.f, 0.f, 0.f);
                if (RELU) {
                    v.x = fmaxf(v.x, 0.f); v.y = fmaxf(v.y, 0.f);
                    v.z = fmaxf(v.z, 0.f); v.w = fmaxf(v.w, 0.f);
                }
                uint32_t h01, l01, h23, l23;
                split2(v.x, v.y, h01, l01);
                split2(v.z, v.w, h23, l23);
                *(uint32_t*)(ah + k4 * 8)     = h01;
                *(uint32_t*)(ah + k4 * 8 + 4) = h23;
                *(uint32_t*)(al + k4 * 8)     = l01;
                *(uint32_t*)(al + k4 * 8 + 4) = l23;
            }
        }
        // ---- B fill: straight uint4 copies from pre-split weights ----
        {
            const int nn = fillRow;
            const uint4* sh = (const uint4*)(whi + (size_t)nn * D + kstage + fillSub);
            const uint4* sl = (const uint4*)(wlo + (size_t)nn * D + kstage + fillSub);
            uint4* bh = (uint4*)(smem + BHI_OFF + nn * LDS_STRIDE_B + fillSub * 2);
            uint4* bl = (uint4*)(smem + BLO_OFF + nn * LDS_STRIDE_B + fillSub * 2);
#pragma unroll
            for (int q = 0; q < 4; q++) { bh[q] = sh[q]; bl[q] = sl[q]; }
        }
        __syncthreads();

#pragma unroll
        for (int ks = 0; ks < 4; ks++) {
            const uint32_t kb = (uint32_t)(ks * 32);
            uint32_t ah0, ah1, ah2, ah3, al0, al1, al2, al3;
            ldmx4(ah0, ah1, ah2, ah3, sb + AHI_OFF + aOffBytes + kb);
            ldmx4(al0, al1, al2, al3, sb + ALO_OFF + aOffBytes + kb);
#pragma unroll
            for (int nc = 0; nc < 8; nc++) {
                const uint32_t bAddr = bOffBytes + (uint32_t)(nc * 16 * LDS_STRIDE_B) + kb;
                uint32_t bh0, bh1, bh2, bh3, bl0, bl1, bl2, bl3;
                ldmx4(bh0, bh1, bh2, bh3, sb + BHI_OFF + bAddr);
                ldmx4(bl0, bl1, bl2, bl3, sb + BLO_OFF + bAddr);
                float* c0 = acc[nc * 2];
                float* c1 = acc[nc * 2 + 1];
                mma_bf16(c0[0], c0[1], c0[2], c0[3], ah0, ah1, ah2, ah3, bh0, bh1);
                mma_bf16(c0[0], c0[1], c0[2], c0[3], ah0, ah1, ah2, ah3, bl0, bl1);
                mma_bf16(c0[0], c0[1], c0[2], c0[3], al0, al1, al2, al3, bh0, bh1);
                mma_bf16(c1[0], c1[1], c1[2], c1[3], ah0, ah1, ah2, ah3, bh2, bh3);
                mma_bf16(c1[0], c1[1], c1[2], c1[3], ah0, ah1, ah2, ah3, bl2, bl3);
                mma_bf16(c1[0], c1[1], c1[2], c1[3], al0, al1, al2, al3, bh2, bh3);
            }
        }
        __syncthreads();
    }

    // ---- epilogue ----
    const int rTop = rbase + m0 + (lane >> 2);
    const int cOff = (lane & 3) * 2;
#pragma unroll
    for (int t = 0; t < 16; t++) {
        const int col = t * 8 + cOff;
        float bx = 0.f, by = 0.f;
        if (BIAS) { bx = bias[col]; by = bias[col + 1]; }
        if (rTop < n) {
            float2 v = make_float2(acc[t][0] + bx, acc[t][1] + by);
            *(float2*)(out + (size_t)rTop * D + col) = v;
        }
        if (rTop + 8 < n) {
            float2 v = make_float2(acc[t][2] + bx, acc[t][3] + by);
            *(float2*)(out + (size_t)(rTop + 8) * D + col) = v;
        }
    }
}

// ---------------- edge-index dtype detection ----------------------------------
__global__ void k_detect(const int* __restrict__ ei32, int E) {
    int odd_zero = 1;
    for (int i = 0; i < 64; i++) if (ei32[2 * i + 1] != 0) { odd_zero = 0; break; }
    g_is64 = odd_zero;
}

// ---------------- degree / norm prep -----------------------------------------
__global__ void k_deg_init(int n) {
    int i = blockIdx.x * blockDim.x + threadIdx.x;
    if (i < n) { g_deg[i] = 1.0f; g_cnt[i] = 0; }
}

__global__ void k_deg_accum(const void* __restrict__ ei_raw,
                            const float* __restrict__ w, int E, int n) {
    int e = blockIdx.x * blockDim.x + threadIdx.x;
    if (e >= E) return;
    int s, d;
    if (g_is64) {
        const long long* ei = (const long long*)ei_raw;
        s = (int)ei[e]; d = (int)ei[E + e];
    } else {
        const int* ei = (const int*)ei_raw;
        s = ei[e]; d = ei[E + e];
    }
    if ((unsigned)s >= (unsigned)n) s = 0;
    if ((unsigned)d >= (unsigned)n) d = 0;
    g_src[e] = s; g_dst[e] = d;
    atomicAdd(&g_deg[d], w[e]);
    atomicAdd(&g_cnt[d], 1);
}

// ---------------- CSR build (scan1 also computes dinv) -------------------------
__global__ void k_scan1(int n) {
    __shared__ int sh[SCAN_B];
    int i = blockIdx.x * SCAN_B + threadIdx.x;
    int v = (i < n) ? g_cnt[i] : 0;
    if (i < n) g_dinv[i] = rsqrtf(g_deg[i]);   // fused: deg >= 1 always
    sh[threadIdx.x] = v;
    __syncthreads();
    for (int o = 1; o < SCAN_B; o <<= 1) {
        int t = (threadIdx.x >= o) ? sh[threadIdx.x - o] : 0;
        __syncthreads();
        sh[threadIdx.x] += t;
        __syncthreads();
    }
    if (i < n) g_rowtmp[i] = sh[threadIdx.x] - v;
    if (threadIdx.x == SCAN_B - 1) g_bsum[blockIdx.x] = sh[SCAN_B - 1];
}

__global__ void k_scan2(int nb) {
    __shared__ int sh[SCAN_B];
    int v = (threadIdx.x < nb) ? g_bsum[threadIdx.x] : 0;
    sh[threadIdx.x] = v;
    __syncthreads();
    for (int o = 1; o < SCAN_B; o <<= 1) {
        int t = (threadIdx.x >= o) ? sh[threadIdx.x - o] : 0;
        __syncthreads();
        sh[threadIdx.x] += t;
        __syncthreads();
    }
    g_boff[threadIdx.x] = sh[threadIdx.x] - v;
}

__global__ void k_scan3(int n, int E) {
    int i = blockIdx.x * blockDim.x + threadIdx.x;
    if (i < n) {
        int r = g_rowtmp[i] + g_boff[i / SCAN_B];
        g_rowptr[i] = r;
        g_ofs[i]    = r;
    }
    if (i == 0) g_rowptr[n] = E;
}

// fill also computes norm inline (k_norm fused away)
__global__ void k_fill(const float* __restrict__ w, int E) {
    int e = blockIdx.x * blockDim.x + threadIdx.x;
    if (e >= E) return;
    int s   = g_src[e];
    int d   = g_dst[e];
    int pos = atomicAdd(&g_ofs[d], 1);
    float nrm = g_dinv[s] * w[e] * g_dinv[d];
    int2 v;
    v.x = s;
    v.y = __float_as_int(nrm);
    g_csr[pos] = v;
}

// ---------------- fused aggregation (gather, no atomics) ----------------------
__global__ void __launch_bounds__(256)
k_agg(const float* __restrict__ bias, int n) {
    int node = (blockIdx.x * blockDim.x + threadIdx.x) >> 5;
    int lane = threadIdx.x & 31;
    if (node >= n) return;

    int beg = g_rowptr[node];
    int end = g_rowptr[node + 1];
    float di = g_dinv[node];
    float s  = di * di;

    float4 hv = *(const float4*)(g_h + (size_t)node * D + lane * 4);
    float4 bv = *(const float4*)(bias + lane * 4);
    float ax = fmaf(hv.x, s, bv.x);
    float ay = fmaf(hv.y, s, bv.y);
    float az = fmaf(hv.z, s, bv.z);
    float aw = fmaf(hv.w, s, bv.w);

    int e = beg;
    for (; e + 3 < end; e += 4) {
        int2 c0 = g_csr[e];
        int2 c1 = g_csr[e + 1];
        int2 c2 = g_csr[e + 2];
        int2 c3 = g_csr[e + 3];
        float4 h0 = *(const float4*)(g_h + (size_t)c0.x * D + lane * 4);
        float4 h1 = *(const float4*)(g_h + (size_t)c1.x * D + lane * 4);
        float4 h2 = *(const float4*)(g_h + (size_t)c2.x * D + lane * 4);
        float4 h3 = *(const float4*)(g_h + (size_t)c3.x * D + lane * 4);
        float n0 = __int_as_float(c0.y), n1 = __int_as_float(c1.y);
        float n2 = __int_as_float(c2.y), n3 = __int_as_float(c3.y);
        ax = fmaf(h0.x, n0, ax); ay = fmaf(h0.y, n0, ay);
        az = fmaf(h0.z, n0, az); aw = fmaf(h0.w, n0, aw);
        ax = fmaf(h1.x, n1, ax); ay = fmaf(h1.y, n1, ay);
        az = fmaf(h1.z, n1, az); aw = fmaf(h1.w, n1, aw);
        ax = fmaf(h2.x, n2, ax); ay = fmaf(h2.y, n2, ay);
        az = fmaf(h2.z, n2, az); aw = fmaf(h2.w, n2, aw);
        ax = fmaf(h3.x, n3, ax); ay = fmaf(h3.y, n3, ay);
        az = fmaf(h3.z, n3, az); aw = fmaf(h3.w, n3, aw);
    }
    for (; e < end; e++) {
        int2 c0 = g_csr[e];
        float n0 = __int_as_float(c0.y);
        float4 h0 = *(const float4*)(g_h + (size_t)c0.x * D + lane * 4);
        ax = fmaf(h0.x, n0, ax); ay = fmaf(h0.y, n0, ay);
        az = fmaf(h0.z, n0, az); aw = fmaf(h0.w, n0, aw);
    }
    *(float4*)(g_out + (size_t)node * D + lane * 4) = make_float4(ax, ay, az, aw);
}

// ---------------- host launcher ----------------------------------------------
extern "C" void kernel_launch(void* const* d_in, const int* in_sizes, int n_in,
                              void* d_out, int out_size) {
    const float* x  = (const float*)d_in[0];
    const void*  ei = d_in[1];
    const float* ew = (const float*)d_in[2];
    const float* W1 = (const float*)d_in[3];
    const float* b1 = (const float*)d_in[4];
    const float* W2 = (const float*)d_in[5];
    const float* b2 = (const float*)d_in[6];
    const float* W3 = (const float*)d_in[7];
    const float* b3 = (const float*)d_in[8];
    const float* Wl = (const float*)d_in[9];
    const float* bl = (const float*)d_in[10];
    float* out = (float*)d_out;

    const int N = in_sizes[0] / D;
    const int E = in_sizes[2];

    float *dh = nullptr, *dout = nullptr;
    unsigned short *whi = nullptr, *wlo = nullptr;
    cudaGetSymbolAddress((void**)&dh,   g_h);
    cudaGetSymbolAddress((void**)&dout, g_out);
    cudaGetSymbolAddress((void**)&whi,  g_whi);
    cudaGetSymbolAddress((void**)&wlo,  g_wlo);

    cudaFuncSetAttribute(k_tgemm<false, false>, cudaFuncAttributeMaxDynamicSharedMemorySize, SM_TOTAL);
    cudaFuncSetAttribute(k_tgemm<true,  false>, cudaFuncAttributeMaxDynamicSharedMemorySize, SM_TOTAL);
    cudaFuncSetAttribute(k_tgemm<false, true>,  cudaFuncAttributeMaxDynamicSharedMemorySize, SM_TOTAL);

    const int T = 256;
    const int gN = (N + T - 1) / T;
    const int gE = (E + T - 1) / T;
    const int gG = (N + TM - 1) / TM;
    const int gA = (N * 32 + T - 1) / T;
    const int nb = (N + SCAN_B - 1) / SCAN_B;

    // --- prep: weight split + gcn_norm + CSR build ---
    k_wsplit   <<<64, dim3(32, 8)>>>(W1, W2, W3, Wl);
    k_detect   <<<1, 1>>>((const int*)ei, E);
    k_deg_init <<<gN, T>>>(N);
    k_deg_accum<<<gE, T>>>(ei, ew, E, N);
    k_scan1    <<<nb, SCAN_B>>>(N);      // also computes dinv
    k_scan2    <<<1,  SCAN_B>>>(nb);
    k_scan3    <<<gN, T>>>(N, E);
    k_fill     <<<gE, T>>>(ew, E);       // also computes norm

    // --- layer 1 ---
    k_tgemm<false, false><<<gG, T, SM_TOTAL>>>(x, whi,             wlo,             nullptr, dh, N);
    k_agg<<<gA, T>>>(b1, N);
    // --- layer 2 ---
    k_tgemm<true, false><<<gG, T, SM_TOTAL>>>(dout, whi + 16384,   wlo + 16384,     nullptr, dh, N);
    k_agg<<<gA, T>>>(b2, N);
    // --- layer 3 ---
    k_tgemm<true, false><<<gG, T, SM_TOTAL>>>(dout, whi + 2 * 16384, wlo + 2 * 16384, nullptr, dh, N);
    k_agg<<<gA, T>>>(b3, N);
    // --- final linear ---
    k_tgemm<false, true><<<gG, T, SM_TOTAL>>>(dout, whi + 3 * 16384, wlo + 3 * 16384, bl, out, N);
}

// round 8
// speedup vs baseline: 2.1621x; 1.0157x over previous
#include <cuda_runtime.h>
#include <cuda_bf16.h>
#include <cstdint>

#define NN 50000
#define NE 800000
#define D  128
#define SCAN_B 256
#define TM 128

#define LDS_STRIDE_B 144
#define AHI_OFF 0
#define ALO_OFF 18432
#define BHI_OFF 36864
#define BLO_OFF 55296
#define SM_TOTAL 73728

// fixed-point scale for packed degree accumulation (22 fraction bits)
#define DEG_SCALE 4194304.0f

// ---------------- scratch (static device globals; no allocation) -------------
__device__ float g_h  [NN * D];
__device__ float g_out[NN * D];
__device__ int   g_src [NE];
__device__ int   g_dst [NE];
__device__ int   g_eidx[NE];                 // within-row slot for each edge
__device__ unsigned long long g_pack[NN];    // high32 = cnt, low32 = fix22(sum w)
__device__ float g_dinv[NN];
__device__ int   g_is64;
// CSR (by dst)
__device__ int   g_rowtmp[NN];
__device__ int   g_rowptr[NN + 1];
__device__ int   g_bsum  [SCAN_B];
__device__ int   g_boff  [SCAN_B];
__device__ int2  g_csr   [NE];               // .x = src, .y = bitcast(norm)
// pre-split transposed weights: [w][nn][k] bf16
__device__ unsigned short g_whi[4 * 16384];
__device__ unsigned short g_wlo[4 * 16384];

// ---------------- helpers ------------------------------------------------------
__device__ __forceinline__ uint32_t smem_u32(const void* p) {
    uint32_t a;
    asm("{ .reg .u64 t; cvta.to.shared.u64 t, %1; cvt.u32.u64 %0, t; }" : "=r"(a) : "l"(p));
    return a;
}

__device__ __forceinline__ void ldmx4(uint32_t& r0, uint32_t& r1, uint32_t& r2,
                                      uint32_t& r3, uint32_t addr) {
    asm volatile("ldmatrix.sync.aligned.m8n8.x4.shared.b16 {%0,%1,%2,%3}, [%4];"
                 : "=r"(r0), "=r"(r1), "=r"(r2), "=r"(r3) : "r"(addr));
}

__device__ __forceinline__ void mma_bf16(float& c0, float& c1, float& c2, float& c3,
                                         uint32_t a0, uint32_t a1, uint32_t a2, uint32_t a3,
                                         uint32_t b0, uint32_t b1) {
    asm volatile("mma.sync.aligned.m16n8k16.row.col.f32.bf16.bf16.f32 "
                 "{%0,%1,%2,%3}, {%4,%5,%6,%7}, {%8,%9}, {%0,%1,%2,%3};"
                 : "+f"(c0), "+f"(c1), "+f"(c2), "+f"(c3)
                 : "r"(a0), "r"(a1), "r"(a2), "r"(a3), "r"(b0), "r"(b1));
}

__device__ __forceinline__ void split2(float x, float y, uint32_t& hi, uint32_t& lo) {
    __nv_bfloat16 hx = __float2bfloat16(x), hy = __float2bfloat16(y);
    __nv_bfloat16 lx = __float2bfloat16(x - __bfloat162float(hx));
    __nv_bfloat16 ly = __float2bfloat16(y - __bfloat162float(hy));
    hi = (uint32_t)__bfloat16_as_ushort(hx) | ((uint32_t)__bfloat16_as_ushort(hy) << 16);
    lo = (uint32_t)__bfloat16_as_ushort(lx) | ((uint32_t)__bfloat16_as_ushort(ly) << 16);
}

// ---------------- weight pre-split (transpose + bf16 hi/lo) -------------------
__global__ void k_wsplit(const float* __restrict__ W0, const float* __restrict__ W1,
                         const float* __restrict__ W2, const float* __restrict__ W3) {
    __shared__ float tile[32][33];
    const int b  = blockIdx.x;
    const int w  = b >> 4;
    const int k0 = ((b >> 2) & 3) * 32;
    const int n0 = (b & 3) * 32;
    const float* W = (w == 0) ? W0 : (w == 1) ? W1 : (w == 2) ? W2 : W3;
    const int tx = threadIdx.x, ty = threadIdx.y;
#pragma unroll
    for (int i = 0; i < 4; i++)
        tile[ty + 8 * i][tx] = W[(size_t)(k0 + ty + 8 * i) * D + n0 + tx];
    __syncthreads();
#pragma unroll
    for (int i = 0; i < 4; i++) {
        float v = tile[tx][ty + 8 * i];
        __nv_bfloat16 h = __float2bfloat16(v);
        __nv_bfloat16 l = __float2bfloat16(v - __bfloat162float(h));
        size_t idx = (size_t)w * 16384 + (size_t)(n0 + ty + 8 * i) * D + k0 + tx;
        g_whi[idx] = __bfloat16_as_ushort(h);
        g_wlo[idx] = __bfloat16_as_ushort(l);
    }
}

// ---------------- tensor-core GEMM: out = act(in) @ W (+bias) ----------------
template <bool RELU, bool BIAS>
__global__ void __launch_bounds__(256)
k_tgemm(const float* __restrict__ in, const unsigned short* __restrict__ whi,
        const unsigned short* __restrict__ wlo,
        const float* __restrict__ bias, float* __restrict__ out, int n) {
    extern __shared__ char smem[];
    const uint32_t sb  = smem_u32(smem);
    const int tid   = threadIdx.x;
    const int wid   = tid >> 5;
    const int lane  = tid & 31;
    const int rbase = blockIdx.x * TM;

    const int m0 = wid * 16;
    const int rowInA = (lane & 7) + ((lane >> 3) & 1) * 8;
    const int kAddA  = (lane >> 4) * 8;
    const uint32_t aOffBytes = (uint32_t)((m0 + rowInA) * LDS_STRIDE_B + kAddA * 2);
    const int rowInB = (lane & 7) + (lane >> 4) * 8;
    const int kAddB  = ((lane >> 3) & 1) * 8;
    const uint32_t bOffBytes = (uint32_t)(rowInB * LDS_STRIDE_B + kAddB * 2);

    float acc[16][4];
#pragma unroll
    for (int t = 0; t < 16; t++) {
        acc[t][0] = 0.f; acc[t][1] = 0.f; acc[t][2] = 0.f; acc[t][3] = 0.f;
    }

    const int fillRow = tid >> 1;
    const int fillSub = (tid & 1) * 32;

#pragma unroll
    for (int stage = 0; stage < 2; stage++) {
        const int kstage = stage * 64;
        {
            const int r = rbase + fillRow;
            const float4* src = (const float4*)(in + (size_t)r * D + kstage + fillSub);
            char* ah = smem + AHI_OFF + fillRow * LDS_STRIDE_B + fillSub * 2;
            char* al = smem + ALO_OFF + fillRow * LDS_STRIDE_B + fillSub * 2;
#pragma unroll
            for (int k4 = 0; k4 < 8; k4++) {
                float4 v = (r < n) ? src[k4] : make_float4(0.f, 0.f, 0.f, 0.f);
                if (RELU) {
                    v.x = fmaxf(v.x, 0.f); v.y = fmaxf(v.y, 0.f);
                    v.z = fmaxf(v.z, 0.f); v.w = fmaxf(v.w, 0.f);
                }
                uint32_t h01, l01, h23, l23;
                split2(v.x, v.y, h01, l01);
                split2(v.z, v.w, h23, l23);
                *(uint32_t*)(ah + k4 * 8)     = h01;
                *(uint32_t*)(ah + k4 * 8 + 4) = h23;
                *(uint32_t*)(al + k4 * 8)     = l01;
                *(uint32_t*)(al + k4 * 8 + 4) = l23;
            }
        }
        {
            const int nn = fillRow;
            const uint4* sh = (const uint4*)(whi + (size_t)nn * D + kstage + fillSub);
            const uint4* sl = (const uint4*)(wlo + (size_t)nn * D + kstage + fillSub);
            uint4* bh = (uint4*)(smem + BHI_OFF + nn * LDS_STRIDE_B + fillSub * 2);
            uint4* bl = (uint4*)(smem + BLO_OFF + nn * LDS_STRIDE_B + fillSub * 2);
#pragma unroll
            for (int q = 0; q < 4; q++) { bh[q] = sh[q]; bl[q] = sl[q]; }
        }
        __syncthreads();

#pragma unroll
        for (int ks = 0; ks < 4; ks++) {
            const uint32_t kb = (uint32_t)(ks * 32);
            uint32_t ah0, ah1, ah2, ah3, al0, al1, al2, al3;
            ldmx4(ah0, ah1, ah2, ah3, sb + AHI_OFF + aOffBytes + kb);
            ldmx4(al0, al1, al2, al3, sb + ALO_OFF + aOffBytes + kb);
#pragma unroll
            for (int nc = 0; nc < 8; nc++) {
                const uint32_t bAddr = bOffBytes + (uint32_t)(nc * 16 * LDS_STRIDE_B) + kb;
                uint32_t bh0, bh1, bh2, bh3, bl0, bl1, bl2, bl3;
                ldmx4(bh0, bh1, bh2, bh3, sb + BHI_OFF + bAddr);
                ldmx4(bl0, bl1, bl2, bl3, sb + BLO_OFF + bAddr);
                float* c0 = acc[nc * 2];
                float* c1 = acc[nc * 2 + 1];
                mma_bf16(c0[0], c0[1], c0[2], c0[3], ah0, ah1, ah2, ah3, bh0, bh1);
                mma_bf16(c0[0], c0[1], c0[2], c0[3], ah0, ah1, ah2, ah3, bl0, bl1);
                mma_bf16(c0[0], c0[1], c0[2], c0[3], al0, al1, al2, al3, bh0, bh1);
                mma_bf16(c1[0], c1[1], c1[2], c1[3], ah0, ah1, ah2, ah3, bh2, bh3);
                mma_bf16(c1[0], c1[1], c1[2], c1[3], ah0, ah1, ah2, ah3, bl2, bl3);
                mma_bf16(c1[0], c1[1], c1[2], c1[3], al0, al1, al2, al3, bh2, bh3);
            }
        }
        __syncthreads();
    }

    const int rTop = rbase + m0 + (lane >> 2);
    const int cOff = (lane & 3) * 2;
#pragma unroll
    for (int t = 0; t < 16; t++) {
        const int col = t * 8 + cOff;
        float bx = 0.f, by = 0.f;
        if (BIAS) { bx = bias[col]; by = bias[col + 1]; }
        if (rTop < n) {
            float2 v = make_float2(acc[t][0] + bx, acc[t][1] + by);
            *(float2*)(out + (size_t)rTop * D + col) = v;
        }
        if (rTop + 8 < n) {
            float2 v = make_float2(acc[t][2] + bx, acc[t][3] + by);
            *(float2*)(out + (size_t)(rTop + 8) * D + col) = v;
        }
    }
}

// ---------------- edge-index dtype detection (parallel) ------------------------
__global__ void k_detect(const int* __restrict__ ei32) {
    // int64 values < 2^31 little-endian look like (lo, 0) pairs
    int nz = (ei32[2 * threadIdx.x + 1] != 0) ? 1 : 0;
    unsigned any = __ballot_sync(0xFFFFFFFFu, nz);
    __shared__ unsigned sh[2];
    if ((threadIdx.x & 31) == 0) sh[threadIdx.x >> 5] = any;
    __syncthreads();
    if (threadIdx.x == 0) g_is64 = ((sh[0] | sh[1]) == 0) ? 1 : 0;
}

// ---------------- zero packed counters ----------------------------------------
__global__ void k_zero(int n) {
    int i = blockIdx.x * blockDim.x + threadIdx.x;
    if (i < n) g_pack[i] = 0ull;
}

// ---------------- degree+count accumulation (single packed atomic) ------------
__global__ void k_deg_accum(const void* __restrict__ ei_raw,
                            const float* __restrict__ w, int E, int n) {
    int e = blockIdx.x * blockDim.x + threadIdx.x;
    if (e >= E) return;
    int s, d;
    if (g_is64) {
        const long long* ei = (const long long*)ei_raw;
        s = (int)ei[e]; d = (int)ei[E + e];
    } else {
        const int* ei = (const int*)ei_raw;
        s = ei[e]; d = ei[E + e];
    }
    if ((unsigned)s >= (unsigned)n) s = 0;
    if ((unsigned)d >= (unsigned)n) d = 0;
    g_src[e] = s; g_dst[e] = d;
    unsigned long long inc = (1ull << 32) |
        (unsigned long long)(unsigned)__float2uint_rn(w[e] * DEG_SCALE);
    unsigned long long old = atomicAdd(&g_pack[d], inc);
    g_eidx[e] = (int)(old >> 32);           // within-row slot, free from the atomic
}

// ---------------- CSR build (scan1 also computes dinv) -------------------------
__global__ void k_scan1(int n) {
    __shared__ int sh[SCAN_B];
    int i = blockIdx.x * SCAN_B + threadIdx.x;
    int v = 0;
    if (i < n) {
        unsigned long long p = g_pack[i];
        v = (int)(p >> 32);
        float deg = 1.0f + (float)(unsigned)(p & 0xFFFFFFFFull) * (1.0f / DEG_SCALE);
        g_dinv[i] = rsqrtf(deg);
    }
    sh[threadIdx.x] = v;
    __syncthreads();
    for (int o = 1; o < SCAN_B; o <<= 1) {
        int t = (threadIdx.x >= o) ? sh[threadIdx.x - o] : 0;
        __syncthreads();
        sh[threadIdx.x] += t;
        __syncthreads();
    }
    if (i < n) g_rowtmp[i] = sh[threadIdx.x] - v;
    if (threadIdx.x == SCAN_B - 1) g_bsum[blockIdx.x] = sh[SCAN_B - 1];
}

__global__ void k_scan2(int nb) {
    __shared__ int sh[SCAN_B];
    int v = (threadIdx.x < nb) ? g_bsum[threadIdx.x] : 0;
    sh[threadIdx.x] = v;
    __syncthreads();
    for (int o = 1; o < SCAN_B; o <<= 1) {
        int t = (threadIdx.x >= o) ? sh[threadIdx.x - o] : 0;
        __syncthreads();
        sh[threadIdx.x] += t;
        __syncthreads();
    }
    g_boff[threadIdx.x] = sh[threadIdx.x] - v;
}

__global__ void k_scan3(int n, int E) {
    int i = blockIdx.x * blockDim.x + threadIdx.x;
    if (i < n) g_rowptr[i] = g_rowtmp[i] + g_boff[i / SCAN_B];
    if (i == 0) g_rowptr[n] = E;
}

// ---------------- fill (atomic-free: slot precomputed in deg_accum) ------------
__global__ void k_fill(const float* __restrict__ w, int E) {
    int e = blockIdx.x * blockDim.x + threadIdx.x;
    if (e >= E) return;
    int s   = g_src[e];
    int d   = g_dst[e];
    int pos = g_rowptr[d] + g_eidx[e];
    float nrm = g_dinv[s] * w[e] * g_dinv[d];
    int2 v;
    v.x = s;
    v.y = __float_as_int(nrm);
    g_csr[pos] = v;
}

// ---------------- fused aggregation (gather, no atomics) ----------------------
__global__ void __launch_bounds__(256)
k_agg(const float* __restrict__ bias, int n) {
    int node = (blockIdx.x * blockDim.x + threadIdx.x) >> 5;
    int lane = threadIdx.x & 31;
    if (node >= n) return;

    int beg = g_rowptr[node];
    int end = g_rowptr[node + 1];
    float di = g_dinv[node];
    float s  = di * di;

    float4 hv = *(const float4*)(g_h + (size_t)node * D + lane * 4);
    float4 bv = *(const float4*)(bias + lane * 4);
    float ax = fmaf(hv.x, s, bv.x);
    float ay = fmaf(hv.y, s, bv.y);
    float az = fmaf(hv.z, s, bv.z);
    float aw = fmaf(hv.w, s, bv.w);

    int e = beg;
    for (; e + 3 < end; e += 4) {
        int2 c0 = g_csr[e];
        int2 c1 = g_csr[e + 1];
        int2 c2 = g_csr[e + 2];
        int2 c3 = g_csr[e + 3];
        float4 h0 = *(const float4*)(g_h + (size_t)c0.x * D + lane * 4);
        float4 h1 = *(const float4*)(g_h + (size_t)c1.x * D + lane * 4);
        float4 h2 = *(const float4*)(g_h + (size_t)c2.x * D + lane * 4);
        float4 h3 = *(const float4*)(g_h + (size_t)c3.x * D + lane * 4);
        float n0 = __int_as_float(c0.y), n1 = __int_as_float(c1.y);
        float n2 = __int_as_float(c2.y), n3 = __int_as_float(c3.y);
        ax = fmaf(h0.x, n0, ax); ay = fmaf(h0.y, n0, ay);
        az = fmaf(h0.z, n0, az); aw = fmaf(h0.w, n0, aw);
        ax = fmaf(h1.x, n1, ax); ay = fmaf(h1.y, n1, ay);
        az = fmaf(h1.z, n1, az); aw = fmaf(h1.w, n1, aw);
        ax = fmaf(h2.x, n2, ax); ay = fmaf(h2.y, n2, ay);
        az = fmaf(h2.z, n2, az); aw = fmaf(h2.w, n2, aw);
        ax = fmaf(h3.x, n3, ax); ay = fmaf(h3.y, n3, ay);
        az = fmaf(h3.z, n3, az); aw = fmaf(h3.w, n3, aw);
    }
    for (; e < end; e++) {
        int2 c0 = g_csr[e];
        float n0 = __int_as_float(c0.y);
        float4 h0 = *(const float4*)(g_h + (size_t)c0.x * D + lane * 4);
        ax = fmaf(h0.x, n0, ax); ay = fmaf(h0.y, n0, ay);
        az = fmaf(h0.z, n0, az); aw = fmaf(h0.w, n0, aw);
    }
    *(float4*)(g_out + (size_t)node * D + lane * 4) = make_float4(ax, ay, az, aw);
}

// ---------------- host launcher ----------------------------------------------
extern "C" void kernel_launch(void* const* d_in, const int* in_sizes, int n_in,
                              void* d_out, int out_size) {
    const float* x  = (const float*)d_in[0];
    const void*  ei = d_in[1];
    const float* ew = (const float*)d_in[2];
    const float* W1 = (const float*)d_in[3];
    const float* b1 = (const float*)d_in[4];
    const float* W2 = (const float*)d_in[5];
    const float* b2 = (const float*)d_in[6];
    const float* W3 = (const float*)d_in[7];
    const float* b3 = (const float*)d_in[8];
    const float* Wl = (const float*)d_in[9];
    const float* bl = (const float*)d_in[10];
    float* out = (float*)d_out;

    const int N = in_sizes[0] / D;
    const int E = in_sizes[2];

    float *dh = nullptr, *dout = nullptr;
    unsigned short *whi = nullptr, *wlo = nullptr;
    cudaGetSymbolAddress((void**)&dh,   g_h);
    cudaGetSymbolAddress((void**)&dout, g_out);
    cudaGetSymbolAddress((void**)&whi,  g_whi);
    cudaGetSymbolAddress((void**)&wlo,  g_wlo);

    cudaFuncSetAttribute(k_tgemm<false, false>, cudaFuncAttributeMaxDynamicSharedMemorySize, SM_TOTAL);
    cudaFuncSetAttribute(k_tgemm<true,  false>, cudaFuncAttributeMaxDynamicSharedMemorySize, SM_TOTAL);
    cudaFuncSetAttribute(k_tgemm<false, true>,  cudaFuncAttributeMaxDynamicSharedMemorySize, SM_TOTAL);

    const int T = 256;
    const int gN = (N + T - 1) / T;
    const int gE = (E + T - 1) / T;
    const int gG = (N + TM - 1) / TM;
    const int gA = (N * 32 + T - 1) / T;
    const int nb = (N + SCAN_B - 1) / SCAN_B;

    // --- prep ---
    k_wsplit   <<<64, dim3(32, 8)>>>(W1, W2, W3, Wl);
    k_detect   <<<1, 64>>>((const int*)ei);
    k_zero     <<<gN, T>>>(N);
    k_deg_accum<<<gE, T>>>(ei, ew, E, N);
    k_scan1    <<<nb, SCAN_B>>>(N);
    k_scan2    <<<1,  SCAN_B>>>(nb);
    k_scan3    <<<gN, T>>>(N, E);
    k_fill     <<<gE, T>>>(ew, E);

    // --- layer 1 ---
    k_tgemm<false, false><<<gG, T, SM_TOTAL>>>(x, whi, wlo, nullptr, dh, N);
    k_agg<<<gA, T>>>(b1, N);
    // --- layer 2 ---
    k_tgemm<true, false><<<gG, T, SM_TOTAL>>>(dout, whi + 16384, wlo + 16384, nullptr, dh, N);
    k_agg<<<gA, T>>>(b2, N);
    // --- layer 3 ---
    k_tgemm<true, false><<<gG, T, SM_TOTAL>>>(dout, whi + 2 * 16384, wlo + 2 * 16384, nullptr, dh, N);
    k_agg<<<gA, T>>>(b3, N);
    // --- final linear ---
    k_tgemm<false, true><<<gG, T, SM_TOTAL>>>(dout, whi + 3 * 16384, wlo + 3 * 16384, bl, out, N);
}

// round 9
// speedup vs baseline: 2.1787x; 1.0076x over previous
#include <cuda_runtime.h>
#include <cuda_bf16.h>
#include <cstdint>

#define NN 50000
#define NE 800000
#define D  128
#define SCAN_B 256
#define TM 128

#define LDS_STRIDE_B 144
#define AHI_OFF 0
#define ALO_OFF 18432
#define BHI_OFF 36864
#define BLO_OFF 55296
#define SM_TOTAL 73728

// fixed-point scale for packed degree accumulation (22 fraction bits)
#define DEG_SCALE 4194304.0f

// ---------------- scratch (static device globals; no allocation) -------------
__device__ float g_h  [NN * D];
__device__ float g_out[NN * D];
__device__ int   g_src [NE];
__device__ int   g_dst [NE];
__device__ int   g_eidx[NE];                 // within-row slot for each edge
__device__ unsigned long long g_pack[NN];    // high32 = cnt, low32 = fix22(sum w)
__device__ float g_dinv[NN];
__device__ int   g_is64;
// CSR (by dst)
__device__ int   g_rowtmp[NN];
__device__ int   g_rowptr[NN + 1];
__device__ int   g_bsum  [SCAN_B];
__device__ int   g_boff  [SCAN_B];
__device__ int2  g_csr   [NE];               // .x = src, .y = bitcast(w)
// pre-split transposed weights: [w][nn][k] bf16
__device__ unsigned short g_whi[4 * 16384];
__device__ unsigned short g_wlo[4 * 16384];

// ---------------- helpers ------------------------------------------------------
__device__ __forceinline__ uint32_t smem_u32(const void* p) {
    uint32_t a;
    asm("{ .reg .u64 t; cvta.to.shared.u64 t, %1; cvt.u32.u64 %0, t; }" : "=r"(a) : "l"(p));
    return a;
}

__device__ __forceinline__ void ldmx4(uint32_t& r0, uint32_t& r1, uint32_t& r2,
                                      uint32_t& r3, uint32_t addr) {
    asm volatile("ldmatrix.sync.aligned.m8n8.x4.shared.b16 {%0,%1,%2,%3}, [%4];"
                 : "=r"(r0), "=r"(r1), "=r"(r2), "=r"(r3) : "r"(addr));
}

__device__ __forceinline__ void mma_bf16(float& c0, float& c1, float& c2, float& c3,
                                         uint32_t a0, uint32_t a1, uint32_t a2, uint32_t a3,
                                         uint32_t b0, uint32_t b1) {
    asm volatile("mma.sync.aligned.m16n8k16.row.col.f32.bf16.bf16.f32 "
                 "{%0,%1,%2,%3}, {%4,%5,%6,%7}, {%8,%9}, {%0,%1,%2,%3};"
                 : "+f"(c0), "+f"(c1), "+f"(c2), "+f"(c3)
                 : "r"(a0), "r"(a1), "r"(a2), "r"(a3), "r"(b0), "r"(b1));
}

__device__ __forceinline__ void split2(float x, float y, uint32_t& hi, uint32_t& lo) {
    __nv_bfloat16 hx = __float2bfloat16(x), hy = __float2bfloat16(y);
    __nv_bfloat16 lx = __float2bfloat16(x - __bfloat162float(hx));
    __nv_bfloat16 ly = __float2bfloat16(y - __bfloat162float(hy));
    hi = (uint32_t)__bfloat16_as_ushort(hx) | ((uint32_t)__bfloat16_as_ushort(hy) << 16);
    lo = (uint32_t)__bfloat16_as_ushort(lx) | ((uint32_t)__bfloat16_as_ushort(ly) << 16);
}

// ---------------- weight pre-split + pack-counter zeroing ---------------------
__global__ void k_wsplit(const float* __restrict__ W0, const float* __restrict__ W1,
                         const float* __restrict__ W2, const float* __restrict__ W3) {
    // fold in zeroing of g_pack (64 blocks x 256 threads, grid-stride)
    for (int i = blockIdx.x * 256 + threadIdx.y * 32 + threadIdx.x; i < NN; i += 64 * 256)
        g_pack[i] = 0ull;

    __shared__ float tile[32][33];
    const int b  = blockIdx.x;
    const int w  = b >> 4;
    const int k0 = ((b >> 2) & 3) * 32;
    const int n0 = (b & 3) * 32;
    const float* W = (w == 0) ? W0 : (w == 1) ? W1 : (w == 2) ? W2 : W3;
    const int tx = threadIdx.x, ty = threadIdx.y;
#pragma unroll
    for (int i = 0; i < 4; i++)
        tile[ty + 8 * i][tx] = W[(size_t)(k0 + ty + 8 * i) * D + n0 + tx];
    __syncthreads();
#pragma unroll
    for (int i = 0; i < 4; i++) {
        float v = tile[tx][ty + 8 * i];
        __nv_bfloat16 h = __float2bfloat16(v);
        __nv_bfloat16 l = __float2bfloat16(v - __bfloat162float(h));
        size_t idx = (size_t)w * 16384 + (size_t)(n0 + ty + 8 * i) * D + k0 + tx;
        g_whi[idx] = __bfloat16_as_ushort(h);
        g_wlo[idx] = __bfloat16_as_ushort(l);
    }
}

// ---------------- tensor-core GEMM: out = act(in) @ W (+bias) (+row scale) ----
template <bool RELU, bool BIAS, bool SCALE>
__global__ void __launch_bounds__(256)
k_tgemm(const float* __restrict__ in, const unsigned short* __restrict__ whi,
        const unsigned short* __restrict__ wlo,
        const float* __restrict__ bias, float* __restrict__ out, int n) {
    extern __shared__ char smem[];
    const uint32_t sb  = smem_u32(smem);
    const int tid   = threadIdx.x;
    const int wid   = tid >> 5;
    const int lane  = tid & 31;
    const int rbase = blockIdx.x * TM;

    const int m0 = wid * 16;
    const int rowInA = (lane & 7) + ((lane >> 3) & 1) * 8;
    const int kAddA  = (lane >> 4) * 8;
    const uint32_t aOffBytes = (uint32_t)((m0 + rowInA) * LDS_STRIDE_B + kAddA * 2);
    const int rowInB = (lane & 7) + (lane >> 4) * 8;
    const int kAddB  = ((lane >> 3) & 1) * 8;
    const uint32_t bOffBytes = (uint32_t)(rowInB * LDS_STRIDE_B + kAddB * 2);

    float acc[16][4];
#pragma unroll
    for (int t = 0; t < 16; t++) {
        acc[t][0] = 0.f; acc[t][1] = 0.f; acc[t][2] = 0.f; acc[t][3] = 0.f;
    }

    const int fillRow = tid >> 1;
    const int fillSub = (tid & 1) * 32;

#pragma unroll
    for (int stage = 0; stage < 2; stage++) {
        const int kstage = stage * 64;
        {
            const int r = rbase + fillRow;
            const float4* src = (const float4*)(in + (size_t)r * D + kstage + fillSub);
            char* ah = smem + AHI_OFF + fillRow * LDS_STRIDE_B + fillSub * 2;
            char* al = smem + ALO_OFF + fillRow * LDS_STRIDE_B + fillSub * 2;
#pragma unroll
            for (int k4 = 0; k4 < 8; k4++) {
                float4 v = (r < n) ? src[k4] : make_float4(0.f, 0.f, 0.f, 0.f);
                if (RELU) {
                    v.x = fmaxf(v.x, 0.f); v.y = fmaxf(v.y, 0.f);
                    v.z = fmaxf(v.z, 0.f); v.w = fmaxf(v.w, 0.f);
                }
                uint32_t h01, l01, h23, l23;
                split2(v.x, v.y, h01, l01);
                split2(v.z, v.w, h23, l23);
                *(uint32_t*)(ah + k4 * 8)     = h01;
                *(uint32_t*)(ah + k4 * 8 + 4) = h23;
                *(uint32_t*)(al + k4 * 8)     = l01;
                *(uint32_t*)(al + k4 * 8 + 4) = l23;
            }
        }
        {
            const int nn = fillRow;
            const uint4* sh = (const uint4*)(whi + (size_t)nn * D + kstage + fillSub);
            const uint4* sl = (const uint4*)(wlo + (size_t)nn * D + kstage + fillSub);
            uint4* bh = (uint4*)(smem + BHI_OFF + nn * LDS_STRIDE_B + fillSub * 2);
            uint4* bl = (uint4*)(smem + BLO_OFF + nn * LDS_STRIDE_B + fillSub * 2);
#pragma unroll
            for (int q = 0; q < 4; q++) { bh[q] = sh[q]; bl[q] = sl[q]; }
        }
        __syncthreads();

#pragma unroll
        for (int ks = 0; ks < 4; ks++) {
            const uint32_t kb = (uint32_t)(ks * 32);
            uint32_t ah0, ah1, ah2, ah3, al0, al1, al2, al3;
            ldmx4(ah0, ah1, ah2, ah3, sb + AHI_OFF + aOffBytes + kb);
            ldmx4(al0, al1, al2, al3, sb + ALO_OFF + aOffBytes + kb);
#pragma unroll
            for (int nc = 0; nc < 8; nc++) {
                const uint32_t bAddr = bOffBytes + (uint32_t)(nc * 16 * LDS_STRIDE_B) + kb;
                uint32_t bh0, bh1, bh2, bh3, bl0, bl1, bl2, bl3;
                ldmx4(bh0, bh1, bh2, bh3, sb + BHI_OFF + bAddr);
                ldmx4(bl0, bl1, bl2, bl3, sb + BLO_OFF + bAddr);
                float* c0 = acc[nc * 2];
                float* c1 = acc[nc * 2 + 1];
                mma_bf16(c0[0], c0[1], c0[2], c0[3], ah0, ah1, ah2, ah3, bh0, bh1);
                mma_bf16(c0[0], c0[1], c0[2], c0[3], ah0, ah1, ah2, ah3, bl0, bl1);
                mma_bf16(c0[0], c0[1], c0[2], c0[3], al0, al1, al2, al3, bh0, bh1);
                mma_bf16(c1[0], c1[1], c1[2], c1[3], ah0, ah1, ah2, ah3, bh2, bh3);
                mma_bf16(c1[0], c1[1], c1[2], c1[3], ah0, ah1, ah2, ah3, bl2, bl3);
                mma_bf16(c1[0], c1[1], c1[2], c1[3], al0, al1, al2, al3, bh2, bh3);
            }
        }
        __syncthreads();
    }

    const int rTop = rbase + m0 + (lane >> 2);
    const int cOff = (lane & 3) * 2;
    float s0 = 1.f, s1 = 1.f;
    if (SCALE) {
        if (rTop < n)     s0 = g_dinv[rTop];
        if (rTop + 8 < n) s1 = g_dinv[rTop + 8];
    }
#pragma unroll
    for (int t = 0; t < 16; t++) {
        const int col = t * 8 + cOff;
        float bx = 0.f, by = 0.f;
        if (BIAS) { bx = bias[col]; by = bias[col + 1]; }
        if (rTop < n) {
            float2 v = make_float2(SCALE ? acc[t][0] * s0 : acc[t][0] + bx,
                                   SCALE ? acc[t][1] * s0 : acc[t][1] + by);
            *(float2*)(out + (size_t)rTop * D + col) = v;
        }
        if (rTop + 8 < n) {
            float2 v = make_float2(SCALE ? acc[t][2] * s1 : acc[t][2] + bx,
                                   SCALE ? acc[t][3] * s1 : acc[t][3] + by);
            *(float2*)(out + (size_t)(rTop + 8) * D + col) = v;
        }
    }
}

// ---------------- edge-index dtype detection (parallel) ------------------------
__global__ void k_detect(const int* __restrict__ ei32) {
    int nz = (ei32[2 * threadIdx.x + 1] != 0) ? 1 : 0;
    unsigned any = __ballot_sync(0xFFFFFFFFu, nz);
    __shared__ unsigned sh[2];
    if ((threadIdx.x & 31) == 0) sh[threadIdx.x >> 5] = any;
    __syncthreads();
    if (threadIdx.x == 0) g_is64 = ((sh[0] | sh[1]) == 0) ? 1 : 0;
}

// ---------------- degree+count accumulation (single packed atomic) ------------
__global__ void k_deg_accum(const void* __restrict__ ei_raw,
                            const float* __restrict__ w, int E, int n) {
    int e = blockIdx.x * blockDim.x + threadIdx.x;
    if (e >= E) return;
    int s, d;
    if (g_is64) {
        const long long* ei = (const long long*)ei_raw;
        s = (int)ei[e]; d = (int)ei[E + e];
    } else {
        const int* ei = (const int*)ei_raw;
        s = ei[e]; d = ei[E + e];
    }
    if ((unsigned)s >= (unsigned)n) s = 0;
    if ((unsigned)d >= (unsigned)n) d = 0;
    g_src[e] = s; g_dst[e] = d;
    unsigned long long inc = (1ull << 32) |
        (unsigned long long)(unsigned)__float2uint_rn(w[e] * DEG_SCALE);
    unsigned long long old = atomicAdd(&g_pack[d], inc);
    g_eidx[e] = (int)(old >> 32);
}

// ---------------- CSR build (scan1 also computes dinv) -------------------------
__global__ void k_scan1(int n) {
    __shared__ int sh[SCAN_B];
    int i = blockIdx.x * SCAN_B + threadIdx.x;
    int v = 0;
    if (i < n) {
        unsigned long long p = g_pack[i];
        v = (int)(p >> 32);
        float deg = 1.0f + (float)(unsigned)(p & 0xFFFFFFFFull) * (1.0f / DEG_SCALE);
        g_dinv[i] = rsqrtf(deg);
    }
    sh[threadIdx.x] = v;
    __syncthreads();
    for (int o = 1; o < SCAN_B; o <<= 1) {
        int t = (threadIdx.x >= o) ? sh[threadIdx.x - o] : 0;
        __syncthreads();
        sh[threadIdx.x] += t;
        __syncthreads();
    }
    if (i < n) g_rowtmp[i] = sh[threadIdx.x] - v;
    if (threadIdx.x == SCAN_B - 1) g_bsum[blockIdx.x] = sh[SCAN_B - 1];
}

__global__ void k_scan2(int nb) {
    __shared__ int sh[SCAN_B];
    int v = (threadIdx.x < nb) ? g_bsum[threadIdx.x] : 0;
    sh[threadIdx.x] = v;
    __syncthreads();
    for (int o = 1; o < SCAN_B; o <<= 1) {
        int t = (threadIdx.x >= o) ? sh[threadIdx.x - o] : 0;
        __syncthreads();
        sh[threadIdx.x] += t;
        __syncthreads();
    }
    g_boff[threadIdx.x] = sh[threadIdx.x] - v;
}

__global__ void k_scan3(int n, int E) {
    int i = blockIdx.x * blockDim.x + threadIdx.x;
    if (i < n) g_rowptr[i] = g_rowtmp[i] + g_boff[i / SCAN_B];
    if (i == 0) g_rowptr[n] = E;
}

// ---------------- fill: csr = (src, raw weight); no gathers --------------------
__global__ void k_fill(const float* __restrict__ w, int E) {
    int e = blockIdx.x * blockDim.x + threadIdx.x;
    if (e >= E) return;
    int d   = g_dst[e];
    int pos = g_rowptr[d] + g_eidx[e];
    int2 v;
    v.x = g_src[e];
    v.y = __float_as_int(w[e]);
    g_csr[pos] = v;
}

// ---------------- fused aggregation: out = dinv[d]*(sum w*h'[s] + h'[d]) + b ---
__global__ void __launch_bounds__(256)
k_agg(const float* __restrict__ bias, int n) {
    int node = (blockIdx.x * blockDim.x + threadIdx.x) >> 5;
    int lane = threadIdx.x & 31;
    if (node >= n) return;

    int beg = g_rowptr[node];
    int end = g_rowptr[node + 1];
    float di = g_dinv[node];

    // acc starts with self term h'[node]
    float4 hv = *(const float4*)(g_h + (size_t)node * D + lane * 4);
    float ax = hv.x, ay = hv.y, az = hv.z, aw = hv.w;

    int e = beg;
    for (; e + 3 < end; e += 4) {
        int2 c0 = g_csr[e];
        int2 c1 = g_csr[e + 1];
        int2 c2 = g_csr[e + 2];
        int2 c3 = g_csr[e + 3];
        float4 h0 = *(const float4*)(g_h + (size_t)c0.x * D + lane * 4);
        float4 h1 = *(const float4*)(g_h + (size_t)c1.x * D + lane * 4);
        float4 h2 = *(const float4*)(g_h + (size_t)c2.x * D + lane * 4);
        float4 h3 = *(const float4*)(g_h + (size_t)c3.x * D + lane * 4);
        float n0 = __int_as_float(c0.y), n1 = __int_as_float(c1.y);
        float n2 = __int_as_float(c2.y), n3 = __int_as_float(c3.y);
        ax = fmaf(h0.x, n0, ax); ay = fmaf(h0.y, n0, ay);
        az = fmaf(h0.z, n0, az); aw = fmaf(h0.w, n0, aw);
        ax = fmaf(h1.x, n1, ax); ay = fmaf(h1.y, n1, ay);
        az = fmaf(h1.z, n1, az); aw = fmaf(h1.w, n1, aw);
        ax = fmaf(h2.x, n2, ax); ay = fmaf(h2.y, n2, ay);
        az = fmaf(h2.z, n2, az); aw = fmaf(h2.w, n2, aw);
        ax = fmaf(h3.x, n3, ax); ay = fmaf(h3.y, n3, ay);
        az = fmaf(h3.z, n3, az); aw = fmaf(h3.w, n3, aw);
    }
    for (; e < end; e++) {
        int2 c0 = g_csr[e];
        float n0 = __int_as_float(c0.y);
        float4 h0 = *(const float4*)(g_h + (size_t)c0.x * D + lane * 4);
        ax = fmaf(h0.x, n0, ax); ay = fmaf(h0.y, n0, ay);
        az = fmaf(h0.z, n0, az); aw = fmaf(h0.w, n0, aw);
    }

    float4 bv = *(const float4*)(bias + lane * 4);
    float4 o = make_float4(fmaf(ax, di, bv.x), fmaf(ay, di, bv.y),
                           fmaf(az, di, bv.z), fmaf(aw, di, bv.w));
    *(float4*)(g_out + (size_t)node * D + lane * 4) = o;
}

// ---------------- host launcher ----------------------------------------------
extern "C" void kernel_launch(void* const* d_in, const int* in_sizes, int n_in,
                              void* d_out, int out_size) {
    const float* x  = (const float*)d_in[0];
    const void*  ei = d_in[1];
    const float* ew = (const float*)d_in[2];
    const float* W1 = (const float*)d_in[3];
    const float* b1 = (const float*)d_in[4];
    const float* W2 = (const float*)d_in[5];
    const float* b2 = (const float*)d_in[6];
    const float* W3 = (const float*)d_in[7];
    const float* b3 = (const float*)d_in[8];
    const float* Wl = (const float*)d_in[9];
    const float* bl = (const float*)d_in[10];
    float* out = (float*)d_out;

    const int N = in_sizes[0] / D;
    const int E = in_sizes[2];

    float *dh = nullptr, *dout = nullptr;
    unsigned short *whi = nullptr, *wlo = nullptr;
    cudaGetSymbolAddress((void**)&dh,   g_h);
    cudaGetSymbolAddress((void**)&dout, g_out);
    cudaGetSymbolAddress((void**)&whi,  g_whi);
    cudaGetSymbolAddress((void**)&wlo,  g_wlo);

    cudaFuncSetAttribute(k_tgemm<false, false, true>, cudaFuncAttributeMaxDynamicSharedMemorySize, SM_TOTAL);
    cudaFuncSetAttribute(k_tgemm<true,  false, true>, cudaFuncAttributeMaxDynamicSharedMemorySize, SM_TOTAL);
    cudaFuncSetAttribute(k_tgemm<false, true, false>, cudaFuncAttributeMaxDynamicSharedMemorySize, SM_TOTAL);

    const int T = 256;
    const int gN = (N + T - 1) / T;
    const int gE = (E + T - 1) / T;
    const int gG = (N + TM - 1) / TM;
    const int gA = (N * 32 + T - 1) / T;
    const int nb = (N + SCAN_B - 1) / SCAN_B;

    // --- prep ---
    k_wsplit   <<<64, dim3(32, 8)>>>(W1, W2, W3, Wl);   // also zeroes g_pack
    k_detect   <<<1, 64>>>((const int*)ei);
    k_deg_accum<<<gE, T>>>(ei, ew, E, N);
    k_scan1    <<<nb, SCAN_B>>>(N);
    k_scan2    <<<1,  SCAN_B>>>(nb);
    k_scan3    <<<gN, T>>>(N, E);
    k_fill     <<<gE, T>>>(ew, E);

    // --- layer 1 ---
    k_tgemm<false, false, true><<<gG, T, SM_TOTAL>>>(x, whi, wlo, nullptr, dh, N);
    k_agg<<<gA, T>>>(b1, N);
    // --- layer 2 ---
    k_tgemm<true, false, true><<<gG, T, SM_TOTAL>>>(dout, whi + 16384, wlo + 16384, nullptr, dh, N);
    k_agg<<<gA, T>>>(b2, N);
    // --- layer 3 ---
    k_tgemm<true, false, true><<<gG, T, SM_TOTAL>>>(dout, whi + 2 * 16384, wlo + 2 * 16384, nullptr, dh, N);
    k_agg<<<gA, T>>>(b3, N);
    // --- final linear ---
    k_tgemm<false, true, false><<<gG, T, SM_TOTAL>>>(dout, whi + 3 * 16384, wlo + 3 * 16384, bl, out, N);
}

// round 10
// speedup vs baseline: 2.2432x; 1.0296x over previous
#include <cuda_runtime.h>
#include <cuda_bf16.h>
#include <cstdint>

#define NN 50000
#define NE 800000
#define D  128
#define SCAN_B 256
#define TM 128

#define LDS_STRIDE_B 144
#define AHI_OFF 0
#define ALO_OFF 18432
#define BHI_OFF 36864
#define BLO_OFF 55296
#define SM_TOTAL 73728

#define DEG_SCALE 4194304.0f

// ---------------- scratch (static device globals; no allocation) -------------
__device__ float g_h  [NN * D];
__device__ float g_out[NN * D];
__device__ int   g_src [NE];
__device__ int   g_dst [NE];
__device__ int   g_eidx[NE];
__device__ unsigned long long g_pack[NN];
__device__ float g_dinv[NN];
// CSR (by dst)
__device__ int   g_rowtmp[NN];
__device__ int   g_rowptr[NN + 1];
__device__ int   g_bsum  [SCAN_B];
__device__ int   g_boff  [SCAN_B];
__device__ int2  g_csr   [NE];               // .x = src, .y = bitcast(norm)
// pre-split transposed weights
__device__ unsigned short g_whi[4 * 16384];
__device__ unsigned short g_wlo[4 * 16384];

// ---------------- helpers ------------------------------------------------------
__device__ __forceinline__ uint32_t smem_u32(const void* p) {
    uint32_t a;
    asm("{ .reg .u64 t; cvta.to.shared.u64 t, %1; cvt.u32.u64 %0, t; }" : "=r"(a) : "l"(p));
    return a;
}

__device__ __forceinline__ void ldmx4(uint32_t& r0, uint32_t& r1, uint32_t& r2,
                                      uint32_t& r3, uint32_t addr) {
    asm volatile("ldmatrix.sync.aligned.m8n8.x4.shared.b16 {%0,%1,%2,%3}, [%4];"
                 : "=r"(r0), "=r"(r1), "=r"(r2), "=r"(r3) : "r"(addr));
}

__device__ __forceinline__ void mma_bf16(float& c0, float& c1, float& c2, float& c3,
                                         uint32_t a0, uint32_t a1, uint32_t a2, uint32_t a3,
                                         uint32_t b0, uint32_t b1) {
    asm volatile("mma.sync.aligned.m16n8k16.row.col.f32.bf16.bf16.f32 "
                 "{%0,%1,%2,%3}, {%4,%5,%6,%7}, {%8,%9}, {%0,%1,%2,%3};"
                 : "+f"(c0), "+f"(c1), "+f"(c2), "+f"(c3)
                 : "r"(a0), "r"(a1), "r"(a2), "r"(a3), "r"(b0), "r"(b1));
}

__device__ __forceinline__ void split2(float x, float y, uint32_t& hi, uint32_t& lo) {
    __nv_bfloat16 hx = __float2bfloat16(x), hy = __float2bfloat16(y);
    __nv_bfloat16 lx = __float2bfloat16(x - __bfloat162float(hx));
    __nv_bfloat16 ly = __float2bfloat16(y - __bfloat162float(hy));
    hi = (uint32_t)__bfloat16_as_ushort(hx) | ((uint32_t)__bfloat16_as_ushort(hy) << 16);
    lo = (uint32_t)__bfloat16_as_ushort(lx) | ((uint32_t)__bfloat16_as_ushort(ly) << 16);
}

// ---------------- weight pre-split (side stream; no edge deps) ----------------
__global__ void k_wsplit(const float* __restrict__ W0, const float* __restrict__ W1,
                         const float* __restrict__ W2, const float* __restrict__ W3) {
    __shared__ float tile[32][33];
    const int b  = blockIdx.x;
    const int w  = b >> 4;
    const int k0 = ((b >> 2) & 3) * 32;
    const int n0 = (b & 3) * 32;
    const float* W = (w == 0) ? W0 : (w == 1) ? W1 : (w == 2) ? W2 : W3;
    const int tx = threadIdx.x, ty = threadIdx.y;
#pragma unroll
    for (int i = 0; i < 4; i++)
        tile[ty + 8 * i][tx] = W[(size_t)(k0 + ty + 8 * i) * D + n0 + tx];
    __syncthreads();
#pragma unroll
    for (int i = 0; i < 4; i++) {
        float v = tile[tx][ty + 8 * i];
        __nv_bfloat16 h = __float2bfloat16(v);
        __nv_bfloat16 l = __float2bfloat16(v - __bfloat162float(h));
        size_t idx = (size_t)w * 16384 + (size_t)(n0 + ty + 8 * i) * D + k0 + tx;
        g_whi[idx] = __bfloat16_as_ushort(h);
        g_wlo[idx] = __bfloat16_as_ushort(l);
    }
}

// ---------------- tensor-core GEMM: out = act(in) @ W (+bias) ----------------
template <bool RELU, bool BIAS>
__global__ void __launch_bounds__(256)
k_tgemm(const float* __restrict__ in, const unsigned short* __restrict__ whi,
        const unsigned short* __restrict__ wlo,
        const float* __restrict__ bias, float* __restrict__ out, int n) {
    extern __shared__ char smem[];
    const uint32_t sb  = smem_u32(smem);
    const int tid   = threadIdx.x;
    const int wid   = tid >> 5;
    const int lane  = tid & 31;
    const int rbase = blockIdx.x * TM;

    const int m0 = wid * 16;
    const int rowInA = (lane & 7) + ((lane >> 3) & 1) * 8;
    const int kAddA  = (lane >> 4) * 8;
    const uint32_t aOffBytes = (uint32_t)((m0 + rowInA) * LDS_STRIDE_B + kAddA * 2);
    const int rowInB = (lane & 7) + (lane >> 4) * 8;
    const int kAddB  = ((lane >> 3) & 1) * 8;
    const uint32_t bOffBytes = (uint32_t)(rowInB * LDS_STRIDE_B + kAddB * 2);

    float acc[16][4];
#pragma unroll
    for (int t = 0; t < 16; t++) {
        acc[t][0] = 0.f; acc[t][1] = 0.f; acc[t][2] = 0.f; acc[t][3] = 0.f;
    }

    const int fillRow = tid >> 1;
    const int fillSub = (tid & 1) * 32;

#pragma unroll
    for (int stage = 0; stage < 2; stage++) {
        const int kstage = stage * 64;
        {
            const int r = rbase + fillRow;
            const float4* src = (const float4*)(in + (size_t)r * D + kstage + fillSub);
            char* ah = smem + AHI_OFF + fillRow * LDS_STRIDE_B + fillSub * 2;
            char* al = smem + ALO_OFF + fillRow * LDS_STRIDE_B + fillSub * 2;
#pragma unroll
            for (int k4 = 0; k4 < 8; k4++) {
                float4 v = (r < n) ? src[k4] : make_float4(0.f, 0.f, 0.f, 0.f);
                if (RELU) {
                    v.x = fmaxf(v.x, 0.f); v.y = fmaxf(v.y, 0.f);
                    v.z = fmaxf(v.z, 0.f); v.w = fmaxf(v.w, 0.f);
                }
                uint32_t h01, l01, h23, l23;
                split2(v.x, v.y, h01, l01);
                split2(v.z, v.w, h23, l23);
                *(uint32_t*)(ah + k4 * 8)     = h01;
                *(uint32_t*)(ah + k4 * 8 + 4) = h23;
                *(uint32_t*)(al + k4 * 8)     = l01;
                *(uint32_t*)(al + k4 * 8 + 4) = l23;
            }
        }
        {
            const int nn = fillRow;
            const uint4* sh = (const uint4*)(whi + (size_t)nn * D + kstage + fillSub);
            const uint4* sl = (const uint4*)(wlo + (size_t)nn * D + kstage + fillSub);
            uint4* bh = (uint4*)(smem + BHI_OFF + nn * LDS_STRIDE_B + fillSub * 2);
            uint4* bl = (uint4*)(smem + BLO_OFF + nn * LDS_STRIDE_B + fillSub * 2);
#pragma unroll
            for (int q = 0; q < 4; q++) { bh[q] = sh[q]; bl[q] = sl[q]; }
        }
        __syncthreads();

#pragma unroll
        for (int ks = 0; ks < 4; ks++) {
            const uint32_t kb = (uint32_t)(ks * 32);
            uint32_t ah0, ah1, ah2, ah3, al0, al1, al2, al3;
            ldmx4(ah0, ah1, ah2, ah3, sb + AHI_OFF + aOffBytes + kb);
            ldmx4(al0, al1, al2, al3, sb + ALO_OFF + aOffBytes + kb);
#pragma unroll
            for (int nc = 0; nc < 8; nc++) {
                const uint32_t bAddr = bOffBytes + (uint32_t)(nc * 16 * LDS_STRIDE_B) + kb;
                uint32_t bh0, bh1, bh2, bh3, bl0, bl1, bl2, bl3;
                ldmx4(bh0, bh1, bh2, bh3, sb + BHI_OFF + bAddr);
                ldmx4(bl0, bl1, bl2, bl3, sb + BLO_OFF + bAddr);
                float* c0 = acc[nc * 2];
                float* c1 = acc[nc * 2 + 1];
                mma_bf16(c0[0], c0[1], c0[2], c0[3], ah0, ah1, ah2, ah3, bh0, bh1);
                mma_bf16(c0[0], c0[1], c0[2], c0[3], ah0, ah1, ah2, ah3, bl0, bl1);
                mma_bf16(c0[0], c0[1], c0[2], c0[3], al0, al1, al2, al3, bh0, bh1);
                mma_bf16(c1[0], c1[1], c1[2], c1[3], ah0, ah1, ah2, ah3, bh2, bh3);
                mma_bf16(c1[0], c1[1], c1[2], c1[3], ah0, ah1, ah2, ah3, bl2, bl3);
                mma_bf16(c1[0], c1[1], c1[2], c1[3], al0, al1, al2, al3, bh2, bh3);
            }
        }
        __syncthreads();
    }

    const int rTop = rbase + m0 + (lane >> 2);
    const int cOff = (lane & 3) * 2;
#pragma unroll
    for (int t = 0; t < 16; t++) {
        const int col = t * 8 + cOff;
        float bx = 0.f, by = 0.f;
        if (BIAS) { bx = bias[col]; by = bias[col + 1]; }
        if (rTop < n) {
            float2 v = make_float2(acc[t][0] + bx, acc[t][1] + by);
            *(float2*)(out + (size_t)rTop * D + col) = v;
        }
        if (rTop + 8 < n) {
            float2 v = make_float2(acc[t][2] + bx, acc[t][3] + by);
            *(float2*)(out + (size_t)(rTop + 8) * D + col) = v;
        }
    }
}

// ---------------- zero packed counters ----------------------------------------
__global__ void k_zero(int n) {
    int i = blockIdx.x * blockDim.x + threadIdx.x;
    if (i < n) g_pack[i] = 0ull;
}

// ---------------- degree+count accumulation (detect folded in) ----------------
__global__ void k_deg_accum(const void* __restrict__ ei_raw,
                            const float* __restrict__ w, int E, int n) {
    // per-block dtype detection: int64 < 2^31 little-endian -> odd words all 0
    __shared__ int s_nz;
    if (threadIdx.x == 0) s_nz = 0;
    __syncthreads();
    if (threadIdx.x < 64) {
        if (((const int*)ei_raw)[2 * threadIdx.x + 1] != 0) s_nz = 1;  // benign race
    }
    __syncthreads();
    const int is64 = (s_nz == 0);

    int e = blockIdx.x * blockDim.x + threadIdx.x;
    if (e >= E) return;
    int s, d;
    if (is64) {
        const long long* ei = (const long long*)ei_raw;
        s = (int)ei[e]; d = (int)ei[E + e];
    } else {
        const int* ei = (const int*)ei_raw;
        s = ei[e]; d = ei[E + e];
    }
    if ((unsigned)s >= (unsigned)n) s = 0;
    if ((unsigned)d >= (unsigned)n) d = 0;
    g_src[e] = s; g_dst[e] = d;
    unsigned long long inc = (1ull << 32) |
        (unsigned long long)(unsigned)__float2uint_rn(w[e] * DEG_SCALE);
    unsigned long long old = atomicAdd(&g_pack[d], inc);
    g_eidx[e] = (int)(old >> 32);
}

// ---------------- CSR build (scan1 also computes dinv) -------------------------
__global__ void k_scan1(int n) {
    __shared__ int sh[SCAN_B];
    int i = blockIdx.x * SCAN_B + threadIdx.x;
    int v = 0;
    if (i < n) {
        unsigned long long p = g_pack[i];
        v = (int)(p >> 32);
        float deg = 1.0f + (float)(unsigned)(p & 0xFFFFFFFFull) * (1.0f / DEG_SCALE);
        g_dinv[i] = rsqrtf(deg);
    }
    sh[threadIdx.x] = v;
    __syncthreads();
    for (int o = 1; o < SCAN_B; o <<= 1) {
        int t = (threadIdx.x >= o) ? sh[threadIdx.x - o] : 0;
        __syncthreads();
        sh[threadIdx.x] += t;
        __syncthreads();
    }
    if (i < n) g_rowtmp[i] = sh[threadIdx.x] - v;
    if (threadIdx.x == SCAN_B - 1) g_bsum[blockIdx.x] = sh[SCAN_B - 1];
}

__global__ void k_scan2(int nb) {
    __shared__ int sh[SCAN_B];
    int v = (threadIdx.x < nb) ? g_bsum[threadIdx.x] : 0;
    sh[threadIdx.x] = v;
    __syncthreads();
    for (int o = 1; o < SCAN_B; o <<= 1) {
        int t = (threadIdx.x >= o) ? sh[threadIdx.x - o] : 0;
        __syncthreads();
        sh[threadIdx.x] += t;
        __syncthreads();
    }
    g_boff[threadIdx.x] = sh[threadIdx.x] - v;
}

__global__ void k_scan3(int n, int E) {
    int i = blockIdx.x * blockDim.x + threadIdx.x;
    if (i < n) g_rowptr[i] = g_rowtmp[i] + g_boff[i / SCAN_B];
    if (i == 0) g_rowptr[n] = E;
}

// ---------------- fill: csr = (src, nrm) ---------------------------------------
__global__ void k_fill(const float* __restrict__ w, int E) {
    int e = blockIdx.x * blockDim.x + threadIdx.x;
    if (e >= E) return;
    int s   = g_src[e];
    int d   = g_dst[e];
    int pos = g_rowptr[d] + g_eidx[e];
    float nrm = g_dinv[s] * w[e] * g_dinv[d];
    int2 v;
    v.x = s;
    v.y = __float_as_int(nrm);
    g_csr[pos] = v;
}

// ---------------- fused aggregation: out = h[i]/deg + b + sum nrm*h[s] --------
__global__ void __launch_bounds__(256)
k_agg(const float* __restrict__ bias, int n) {
    int node = (blockIdx.x * blockDim.x + threadIdx.x) >> 5;
    int lane = threadIdx.x & 31;
    if (node >= n) return;

    int beg = g_rowptr[node];
    int end = g_rowptr[node + 1];
    float di = g_dinv[node];
    float s  = di * di;

    float4 hv = *(const float4*)(g_h + (size_t)node * D + lane * 4);
    float4 bv = *(const float4*)(bias + lane * 4);
    float ax = fmaf(hv.x, s, bv.x);
    float ay = fmaf(hv.y, s, bv.y);
    float az = fmaf(hv.z, s, bv.z);
    float aw = fmaf(hv.w, s, bv.w);

    int e = beg;
    for (; e + 3 < end; e += 4) {
        int2 c0 = g_csr[e];
        int2 c1 = g_csr[e + 1];
        int2 c2 = g_csr[e + 2];
        int2 c3 = g_csr[e + 3];
        float4 h0 = *(const float4*)(g_h + (size_t)c0.x * D + lane * 4);
        float4 h1 = *(const float4*)(g_h + (size_t)c1.x * D + lane * 4);
        float4 h2 = *(const float4*)(g_h + (size_t)c2.x * D + lane * 4);
        float4 h3 = *(const float4*)(g_h + (size_t)c3.x * D + lane * 4);
        float n0 = __int_as_float(c0.y), n1 = __int_as_float(c1.y);
        float n2 = __int_as_float(c2.y), n3 = __int_as_float(c3.y);
        ax = fmaf(h0.x, n0, ax); ay = fmaf(h0.y, n0, ay);
        az = fmaf(h0.z, n0, az); aw = fmaf(h0.w, n0, aw);
        ax = fmaf(h1.x, n1, ax); ay = fmaf(h1.y, n1, ay);
        az = fmaf(h1.z, n1, az); aw = fmaf(h1.w, n1, aw);
        ax = fmaf(h2.x, n2, ax); ay = fmaf(h2.y, n2, ay);
        az = fmaf(h2.z, n2, az); aw = fmaf(h2.w, n2, aw);
        ax = fmaf(h3.x, n3, ax); ay = fmaf(h3.y, n3, ay);
        az = fmaf(h3.z, n3, az); aw = fmaf(h3.w, n3, aw);
    }
    for (; e < end; e++) {
        int2 c0 = g_csr[e];
        float n0 = __int_as_float(c0.y);
        float4 h0 = *(const float4*)(g_h + (size_t)c0.x * D + lane * 4);
        ax = fmaf(h0.x, n0, ax); ay = fmaf(h0.y, n0, ay);
        az = fmaf(h0.z, n0, az); aw = fmaf(h0.w, n0, aw);
    }
    *(float4*)(g_out + (size_t)node * D + lane * 4) = make_float4(ax, ay, az, aw);
}

// ---------------- host launcher ----------------------------------------------
extern "C" void kernel_launch(void* const* d_in, const int* in_sizes, int n_in,
                              void* d_out, int out_size) {
    const float* x  = (const float*)d_in[0];
    const void*  ei = d_in[1];
    const float* ew = (const float*)d_in[2];
    const float* W1 = (const float*)d_in[3];
    const float* b1 = (const float*)d_in[4];
    const float* W2 = (const float*)d_in[5];
    const float* b2 = (const float*)d_in[6];
    const float* W3 = (const float*)d_in[7];
    const float* b3 = (const float*)d_in[8];
    const float* Wl = (const float*)d_in[9];
    const float* bl = (const float*)d_in[10];
    float* out = (float*)d_out;

    const int N = in_sizes[0] / D;
    const int E = in_sizes[2];

    float *dh = nullptr, *dout = nullptr;
    unsigned short *whi = nullptr, *wlo = nullptr;
    cudaGetSymbolAddress((void**)&dh,   g_h);
    cudaGetSymbolAddress((void**)&dout, g_out);
    cudaGetSymbolAddress((void**)&whi,  g_whi);
    cudaGetSymbolAddress((void**)&wlo,  g_wlo);

    cudaFuncSetAttribute(k_tgemm<false, false>, cudaFuncAttributeMaxDynamicSharedMemorySize, SM_TOTAL);
    cudaFuncSetAttribute(k_tgemm<true,  false>, cudaFuncAttributeMaxDynamicSharedMemorySize, SM_TOTAL);
    cudaFuncSetAttribute(k_tgemm<false, true>,  cudaFuncAttributeMaxDynamicSharedMemorySize, SM_TOTAL);

    // lazily created side stream + fork/join events (host resources, not device mem)
    static cudaStream_t s_side = nullptr;
    static cudaEvent_t  s_fork = nullptr, s_join = nullptr;
    if (!s_side) {
        cudaStreamCreateWithFlags(&s_side, cudaStreamNonBlocking);
        cudaEventCreateWithFlags(&s_fork, cudaEventDisableTiming);
        cudaEventCreateWithFlags(&s_join, cudaEventDisableTiming);
    }

    const int T = 256;
    const int gN = (N + T - 1) / T;
    const int gE = (E + T - 1) / T;
    const int gG = (N + TM - 1) / TM;
    const int gA = (N * 32 + T - 1) / T;
    const int nb = (N + SCAN_B - 1) / SCAN_B;

    // --- fork: side stream does weight split + layer-1 GEMM (no edge deps) ---
    cudaEventRecord(s_fork, 0);
    cudaStreamWaitEvent(s_side, s_fork, 0);
    k_wsplit<<<64, dim3(32, 8), 0, s_side>>>(W1, W2, W3, Wl);
    k_tgemm<false, false><<<gG, T, SM_TOTAL, s_side>>>(x, whi, wlo, nullptr, dh, N);
    cudaEventRecord(s_join, s_side);

    // --- main stream: edge prep chain (runs concurrently with side) ---
    k_zero     <<<gN, T>>>(N);
    k_deg_accum<<<gE, T>>>(ei, ew, E, N);
    k_scan1    <<<nb, SCAN_B>>>(N);
    k_scan2    <<<1,  SCAN_B>>>(nb);
    k_scan3    <<<gN, T>>>(N, E);
    k_fill     <<<gE, T>>>(ew, E);

    // --- join: agg needs both g_h (side) and CSR (main) ---
    cudaStreamWaitEvent(0, s_join, 0);
    k_agg<<<gA, T>>>(b1, N);
    // --- layer 2 ---
    k_tgemm<true, false><<<gG, T, SM_TOTAL>>>(dout, whi + 16384, wlo + 16384, nullptr, dh, N);
    k_agg<<<gA, T>>>(b2, N);
    // --- layer 3 ---
    k_tgemm<true, false><<<gG, T, SM_TOTAL>>>(dout, whi + 2 * 16384, wlo + 2 * 16384, nullptr, dh, N);
    k_agg<<<gA, T>>>(b3, N);
    // --- final linear ---
    k_tgemm<false, true><<<gG, T, SM_TOTAL>>>(dout, whi + 3 * 16384, wlo + 3 * 16384, bl, out, N);
}